// round 6
// baseline (speedup 1.0000x reference)
#include <cuda_runtime.h>
#include <cuda_bf16.h>
#include <stdint.h>

#define MAXN 100000
#define MAXE 1600000
#define C    128

// ---------------- static device scratch (referenced directly by kernels) ----------------
__device__ float g_deg[MAXN];
__device__ float g_dinv[MAXN];
__device__ int   g_count[MAXN];
__device__ int   g_off[MAXN + 1];
__device__ int   g_cursor[MAXN];
__device__ int   g_bsum[1024];
__device__ int   g_bsumscan[1024];
__device__ int2  g_edat[MAXE];            // (src, norm-bits) grouped by dst
__device__ float g_xw[(size_t)MAXN * C];  // h @ W scratch
__device__ float g_hA[(size_t)MAXN * C];
__device__ float g_hB[(size_t)MAXN * C];
__device__ int   g_idx32;                 // 1 if edge_index stored as int32

// ---------------- dtype detection ----------------
// If the index buffer is int64 (values < 2^31), every odd 32-bit word is 0.
// If it is int32, odd words are real node indices -> OR over 3.2M words != 0.
// Reads exactly 2E 32-bit words: in-bounds for BOTH dtypes.
__global__ void k_detect(const unsigned int* __restrict__ w, int nwords) {
    int i = blockIdx.x * blockDim.x + threadIdx.x;
    unsigned int v = (i < nwords && (i & 1)) ? w[i] : 0u;
#pragma unroll
    for (int o = 16; o; o >>= 1) v |= __shfl_down_sync(0xffffffffu, v, o);
    if ((threadIdx.x & 31) == 0 && v) atomicOr(&g_idx32, 1);
}

__device__ __forceinline__ void load_edge(const void* ei, int i, int e, int& r, int& c) {
    if (g_idx32) {
        const int* p = (const int*)ei;
        r = p[i]; c = p[e + i];
    } else {
        const long long* p = (const long long*)ei;
        r = (int)p[i]; c = (int)p[e + i];
    }
}

// ---------------- precompute ----------------
__global__ void k_init(int n) {
    int i = blockIdx.x * blockDim.x + threadIdx.x;
    if (i < n) { g_deg[i] = 1.0f; g_count[i] = 0; }   // 1.0 = self-loop weight
    if (i == 0) g_idx32 = 0;
}

__global__ void k_prep(const void* __restrict__ ei, const float* __restrict__ ea, int e, int n) {
    int i = blockIdx.x * blockDim.x + threadIdx.x;
    if (i >= e) return;
    int r, c;
    load_edge(ei, i, e, r, c);
    if ((unsigned)r >= (unsigned)n || (unsigned)c >= (unsigned)n) return;  // defensive
    atomicAdd(&g_deg[c], ea[i]);
    atomicAdd(&g_count[c], 1);
}

__global__ void k_dinv(int n) {
    int i = blockIdx.x * blockDim.x + threadIdx.x;
    if (i < n) g_dinv[i] = rsqrtf(g_deg[i]);   // deg >= 1 always
}

// exclusive scan of g_count -> g_off, block sums -> g_bsum
__global__ void k_scan1(int n) {
    __shared__ int sh[1024];
    int gid = blockIdx.x * 1024 + threadIdx.x;
    int v = (gid < n) ? g_count[gid] : 0;
    sh[threadIdx.x] = v;
    __syncthreads();
    for (int off = 1; off < 1024; off <<= 1) {
        int t = 0;
        if ((int)threadIdx.x >= off) t = sh[threadIdx.x - off];
        __syncthreads();
        sh[threadIdx.x] += t;
        __syncthreads();
    }
    if (gid < n) g_off[gid] = sh[threadIdx.x] - v;
    if (threadIdx.x == 1023) g_bsum[blockIdx.x] = sh[1023];
}

// exclusive scan of g_bsum -> g_bsumscan (single block)
__global__ void k_scan2(int nb) {
    __shared__ int sh[1024];
    int v = ((int)threadIdx.x < nb) ? g_bsum[threadIdx.x] : 0;
    sh[threadIdx.x] = v;
    __syncthreads();
    for (int off = 1; off < 1024; off <<= 1) {
        int t = 0;
        if ((int)threadIdx.x >= off) t = sh[threadIdx.x - off];
        __syncthreads();
        sh[threadIdx.x] += t;
        __syncthreads();
    }
    if ((int)threadIdx.x < nb) g_bsumscan[threadIdx.x] = sh[threadIdx.x] - v;
}

__global__ void k_scan3(int n, int ecnt) {
    int gid = blockIdx.x * 1024 + threadIdx.x;
    if (gid < n) {
        int v = g_off[gid] + g_bsumscan[blockIdx.x];
        g_off[gid]    = v;
        g_cursor[gid] = v;
    }
    if (gid == 0) g_off[n] = ecnt;   // valid edges end; padded below counts match
}

__global__ void k_scatter(const void* __restrict__ ei, const float* __restrict__ ea, int e, int n) {
    int i = blockIdx.x * blockDim.x + threadIdx.x;
    if (i >= e) return;
    int r, c;
    load_edge(ei, i, e, r, c);
    if ((unsigned)r >= (unsigned)n || (unsigned)c >= (unsigned)n) return;
    float nm = g_dinv[r] * ea[i] * g_dinv[c];
    int pos = atomicAdd(&g_cursor[c], 1);
    g_edat[pos] = make_int2(r, __float_as_int(nm));
}

// Fix g_off[n]: last node's end = cursor[n-1] after scatter (handles skipped edges).
__global__ void k_fixend(int n) {
    if (blockIdx.x == 0 && threadIdx.x == 0) g_off[n] = g_cursor[n - 1];
}

// ---------------- dense GEMM: g_xw = src @ W ----------------
// src selector: 0 = harness x, 1 = g_hA, 2 = g_hB
__global__ void __launch_bounds__(256) k_gemm(const float* __restrict__ Xext,
                                              const float* __restrict__ W,
                                              int src, int n) {
    const float* __restrict__ X = (src == 0) ? Xext : (src == 1 ? g_hA : g_hB);
    __shared__ float Xs[16][64];
    __shared__ float Ws[16][128];
    int row0 = blockIdx.x * 64;
    int tx = threadIdx.x;
    int rg = tx & 15;
    int cg = tx >> 4;
    float acc[4][8];
#pragma unroll
    for (int i = 0; i < 4; i++)
#pragma unroll
        for (int j = 0; j < 8; j++) acc[i][j] = 0.0f;

    for (int k0 = 0; k0 < 128; k0 += 16) {
        {
            int r  = tx >> 2;
            int kb = (tx & 3) * 4;
            int grow = row0 + r;
            float4 v = make_float4(0.f, 0.f, 0.f, 0.f);
            if (grow < n) v = *(const float4*)&X[(size_t)grow * C + k0 + kb];
            Xs[kb + 0][r] = v.x; Xs[kb + 1][r] = v.y;
            Xs[kb + 2][r] = v.z; Xs[kb + 3][r] = v.w;
        }
#pragma unroll
        for (int i = 0; i < 2; i++) {
            int t  = tx + i * 256;
            int kk = t >> 5;
            int c4 = (t & 31) * 4;
            float4 w = *(const float4*)&W[(k0 + kk) * C + c4];
            Ws[kk][c4 + 0] = w.x; Ws[kk][c4 + 1] = w.y;
            Ws[kk][c4 + 2] = w.z; Ws[kk][c4 + 3] = w.w;
        }
        __syncthreads();
#pragma unroll
        for (int kk = 0; kk < 16; kk++) {
            float4 a4 = *(const float4*)&Xs[kk][rg * 4];
            float4 b0 = *(const float4*)&Ws[kk][cg * 8];
            float4 b1 = *(const float4*)&Ws[kk][cg * 8 + 4];
            float a[4] = {a4.x, a4.y, a4.z, a4.w};
            float b[8] = {b0.x, b0.y, b0.z, b0.w, b1.x, b1.y, b1.z, b1.w};
#pragma unroll
            for (int i = 0; i < 4; i++)
#pragma unroll
                for (int j = 0; j < 8; j++) acc[i][j] = fmaf(a[i], b[j], acc[i][j]);
        }
        __syncthreads();
    }
#pragma unroll
    for (int i = 0; i < 4; i++) {
        int grow = row0 + rg * 4 + i;
        if (grow < n) {
            *(float4*)&g_xw[(size_t)grow * C + cg * 8]     = make_float4(acc[i][0], acc[i][1], acc[i][2], acc[i][3]);
            *(float4*)&g_xw[(size_t)grow * C + cg * 8 + 4] = make_float4(acc[i][4], acc[i][5], acc[i][6], acc[i][7]);
        }
    }
}

// ---------------- aggregation: dst[i] = relu(sum_in nm*xw[src] + dinv^2*xw[i] + b) ----------------
// one warp per node; lane owns channels lane*4..lane*4+3. dst: 0 = g_hA, 1 = g_hB
__global__ void __launch_bounds__(256) k_agg(const float* __restrict__ bias, int dst, int n) {
    const float4* __restrict__ xw = (const float4*)g_xw;
    float4* __restrict__ out = dst ? (float4*)g_hB : (float4*)g_hA;
    int warp = (blockIdx.x * blockDim.x + threadIdx.x) >> 5;
    int lane = threadIdx.x & 31;
    if (warp >= n) return;
    float dv = g_dinv[warp];
    float sw = dv * dv;                        // self-loop norm
    float4 v = xw[(size_t)warp * 32 + lane];
    float a0 = sw * v.x, a1 = sw * v.y, a2 = sw * v.z, a3 = sw * v.w;
    int s = g_off[warp], e = g_off[warp + 1];
    for (int j = s; j < e; j++) {
        int2 ed = g_edat[j];                   // warp-uniform load
        float nm = __int_as_float(ed.y);
        float4 u = xw[(size_t)ed.x * 32 + lane];
        a0 = fmaf(nm, u.x, a0);
        a1 = fmaf(nm, u.y, a1);
        a2 = fmaf(nm, u.z, a2);
        a3 = fmaf(nm, u.w, a3);
    }
    float4 bb = ((const float4*)bias)[lane];
    float4 r;
    r.x = fmaxf(a0 + bb.x, 0.f);
    r.y = fmaxf(a1 + bb.y, 0.f);
    r.z = fmaxf(a2 + bb.z, 0.f);
    r.w = fmaxf(a3 + bb.w, 0.f);
    out[(size_t)warp * 32 + lane] = r;
}

// ---------------- head: out[i] = hA[i,:] . lin_w + lin_b ----------------
__global__ void __launch_bounds__(256) k_linear(const float* __restrict__ lw,
                                                const float* __restrict__ lb,
                                                float* __restrict__ out, int n) {
    const float4* __restrict__ h = (const float4*)g_hA;
    int warp = (blockIdx.x * blockDim.x + threadIdx.x) >> 5;
    int lane = threadIdx.x & 31;
    if (warp >= n) return;
    float4 v = h[(size_t)warp * 32 + lane];
    float4 w = ((const float4*)lw)[lane];
    float s = v.x * w.x + v.y * w.y + v.z * w.z + v.w * w.w;
#pragma unroll
    for (int o = 16; o; o >>= 1) s += __shfl_down_sync(0xffffffffu, s, o);
    if (lane == 0) out[warp] = s + lb[0];
}

// ---------------- host launch (kernel launches ONLY — no runtime API calls) ----------------
extern "C" void kernel_launch(void* const* d_in, const int* in_sizes, int n_in,
                              void* d_out, int out_size) {
    const float* x  = (const float*)d_in[0];
    const void*  ei = d_in[1];                 // int32 or int64, detected on device
    const float* ea = (const float*)d_in[2];
    const float* W1 = (const float*)d_in[3];
    const float* b1 = (const float*)d_in[4];
    const float* W2 = (const float*)d_in[5];
    const float* b2 = (const float*)d_in[6];
    const float* W3 = (const float*)d_in[7];
    const float* b3 = (const float*)d_in[8];
    const float* lw = (const float*)d_in[9];
    const float* lb = (const float*)d_in[10];
    float* outp = (float*)d_out;

    const int n = in_sizes[0] / C;    // 100000
    const int e = in_sizes[2];        // 1600000 (edge_attr element count)

    const int nbN    = (n + 255) / 256;
    const int nbE    = (e + 255) / 256;
    const int nbScan = (n + 1023) / 1024;
    const int nbDet  = (2 * e + 255) / 256;

    // ---- normalization + CSC build ----
    k_init   <<<nbN, 256>>>(n);
    k_detect <<<nbDet, 256>>>((const unsigned int*)ei, 2 * e);
    k_prep   <<<nbE, 256>>>(ei, ea, e, n);
    k_dinv   <<<nbN, 256>>>(n);
    k_scan1  <<<nbScan, 1024>>>(n);
    k_scan2  <<<1, 1024>>>(nbScan);
    k_scan3  <<<nbScan, 1024>>>(n, e);
    k_scatter<<<nbE, 256>>>(ei, ea, e, n);
    k_fixend <<<1, 32>>>(n);

    const int nbG = (n + 63) / 64;
    const int nbW = (n * 32 + 255) / 256;

    // ---- layer 1 ----
    k_gemm<<<nbG, 256>>>(x, W1, 0, n);
    k_agg <<<nbW, 256>>>(b1, 0, n);            // -> hA
    // ---- layer 2 ----
    k_gemm<<<nbG, 256>>>(x, W2, 1, n);         // src = hA
    k_agg <<<nbW, 256>>>(b2, 1, n);            // -> hB
    // ---- layer 3 ----
    k_gemm<<<nbG, 256>>>(x, W3, 2, n);         // src = hB
    k_agg <<<nbW, 256>>>(b3, 0, n);            // -> hA
    // ---- head ----
    k_linear<<<nbW, 256>>>(lw, lb, outp, n);
}

// round 7
// speedup vs baseline: 1.0273x; 1.0273x over previous
#include <cuda_runtime.h>
#include <cuda_bf16.h>
#include <stdint.h>

#define MAXN 100000
#define MAXE 1600000
#define C    128

// ---------------- static device scratch ----------------
__device__ float g_deg[MAXN];
__device__ float g_dinv[MAXN];
__device__ int   g_count[MAXN];
__device__ int   g_off[MAXN + 1];
__device__ int   g_cursor[MAXN];
__device__ int   g_bsum[1024];
__device__ int   g_bsumscan[1024];
__device__ int2  g_edat[MAXE];            // (src, norm-bits) grouped by dst
__device__ float g_xw[(size_t)MAXN * C];  // h @ W scratch
__device__ float g_hA[(size_t)MAXN * C];
__device__ float g_hB[(size_t)MAXN * C];
__device__ int   g_idx32;                 // 1 if edge_index stored as int32

// ---------------- packed f32x2 helpers (sm_103a FFMA2) ----------------
__device__ __forceinline__ unsigned long long ffma2(unsigned long long a,
                                                    unsigned long long b,
                                                    unsigned long long c) {
    unsigned long long d;
    asm("fma.rn.f32x2 %0, %1, %2, %3;" : "=l"(d) : "l"(a), "l"(b), "l"(c));
    return d;
}
__device__ __forceinline__ unsigned long long dup2(float x) {
    unsigned long long d;
    asm("mov.b64 %0, {%1, %1};" : "=l"(d) : "f"(x));
    return d;
}
__device__ __forceinline__ float2 unpack2(unsigned long long v) {
    float lo, hi;
    asm("mov.b64 {%0, %1}, %2;" : "=f"(lo), "=f"(hi) : "l"(v));
    return make_float2(lo, hi);
}

// ---------------- dtype detection ----------------
// int64 indices (< 2^31): every odd 32-bit word is 0. int32: OR of odd words != 0.
// Reads exactly 2E words -> in-bounds for both dtypes.
__global__ void k_detect(const unsigned int* __restrict__ w, int nwords) {
    int i = blockIdx.x * blockDim.x + threadIdx.x;
    unsigned int v = (i < nwords && (i & 1)) ? w[i] : 0u;
#pragma unroll
    for (int o = 16; o; o >>= 1) v |= __shfl_down_sync(0xffffffffu, v, o);
    if ((threadIdx.x & 31) == 0 && v) atomicOr(&g_idx32, 1);
}

__device__ __forceinline__ void load_edge(const void* ei, int i, int e, int& r, int& c) {
    if (g_idx32) {
        const int* p = (const int*)ei;
        r = p[i]; c = p[e + i];
    } else {
        const long long* p = (const long long*)ei;
        r = (int)p[i]; c = (int)p[e + i];
    }
}

// ---------------- precompute ----------------
__global__ void k_init(int n) {
    int i = blockIdx.x * blockDim.x + threadIdx.x;
    if (i < n) { g_deg[i] = 1.0f; g_count[i] = 0; }   // 1.0 = self-loop weight
    if (i == 0) g_idx32 = 0;
}

__global__ void k_prep(const void* __restrict__ ei, const float* __restrict__ ea, int e, int n) {
    int i = blockIdx.x * blockDim.x + threadIdx.x;
    if (i >= e) return;
    int r, c;
    load_edge(ei, i, e, r, c);
    if ((unsigned)r >= (unsigned)n || (unsigned)c >= (unsigned)n) return;
    atomicAdd(&g_deg[c], ea[i]);
    atomicAdd(&g_count[c], 1);
}

__global__ void k_dinv(int n) {
    int i = blockIdx.x * blockDim.x + threadIdx.x;
    if (i < n) g_dinv[i] = rsqrtf(g_deg[i]);
}

__global__ void k_scan1(int n) {
    __shared__ int sh[1024];
    int gid = blockIdx.x * 1024 + threadIdx.x;
    int v = (gid < n) ? g_count[gid] : 0;
    sh[threadIdx.x] = v;
    __syncthreads();
    for (int off = 1; off < 1024; off <<= 1) {
        int t = 0;
        if ((int)threadIdx.x >= off) t = sh[threadIdx.x - off];
        __syncthreads();
        sh[threadIdx.x] += t;
        __syncthreads();
    }
    if (gid < n) g_off[gid] = sh[threadIdx.x] - v;
    if (threadIdx.x == 1023) g_bsum[blockIdx.x] = sh[1023];
}

__global__ void k_scan2(int nb) {
    __shared__ int sh[1024];
    int v = ((int)threadIdx.x < nb) ? g_bsum[threadIdx.x] : 0;
    sh[threadIdx.x] = v;
    __syncthreads();
    for (int off = 1; off < 1024; off <<= 1) {
        int t = 0;
        if ((int)threadIdx.x >= off) t = sh[threadIdx.x - off];
        __syncthreads();
        sh[threadIdx.x] += t;
        __syncthreads();
    }
    if ((int)threadIdx.x < nb) g_bsumscan[threadIdx.x] = sh[threadIdx.x] - v;
}

__global__ void k_scan3(int n, int ecnt) {
    int gid = blockIdx.x * 1024 + threadIdx.x;
    if (gid < n) {
        int v = g_off[gid] + g_bsumscan[blockIdx.x];
        g_off[gid]    = v;
        g_cursor[gid] = v;
    }
    if (gid == 0) g_off[n] = ecnt;
}

__global__ void k_scatter(const void* __restrict__ ei, const float* __restrict__ ea, int e, int n) {
    int i = blockIdx.x * blockDim.x + threadIdx.x;
    if (i >= e) return;
    int r, c;
    load_edge(ei, i, e, r, c);
    if ((unsigned)r >= (unsigned)n || (unsigned)c >= (unsigned)n) return;
    float nm = g_dinv[r] * ea[i] * g_dinv[c];
    int pos = atomicAdd(&g_cursor[c], 1);
    g_edat[pos] = make_int2(r, __float_as_int(nm));
}

__global__ void k_fixend(int n) {
    if (blockIdx.x == 0 && threadIdx.x == 0) g_off[n] = g_cursor[n - 1];
}

// ---------------- dense GEMM (FFMA2): g_xw = src @ W ----------------
// 128x128 tile per block, 256 threads, 8x8 per-thread tile as 8x4 packed f32x2.
// src selector: 0 = harness x, 1 = g_hA, 2 = g_hB
__global__ void __launch_bounds__(256) k_gemm(const float* __restrict__ Xext,
                                              const float* __restrict__ W,
                                              int src, int n) {
    const float* __restrict__ X = (src == 0) ? Xext : (src == 1 ? g_hA : g_hB);
    __shared__ float Xs[16][128];   // k-major
    __shared__ float Ws[16][128];
    int row0 = blockIdx.x * 128;
    int tx = threadIdx.x;
    int rg = tx & 15;     // rows rg*8 .. rg*8+7
    int cg = tx >> 4;     // cols cg*8 .. cg*8+7

    unsigned long long acc[8][4];
#pragma unroll
    for (int i = 0; i < 8; i++)
#pragma unroll
        for (int j = 0; j < 4; j++) acc[i][j] = 0ull;

    for (int k0 = 0; k0 < 128; k0 += 16) {
        // X tile: 128 rows x 16 k -> 512 float4, 2 per thread
#pragma unroll
        for (int i = 0; i < 2; i++) {
            int t  = tx + i * 256;
            int r  = t >> 2;             // 0..127
            int kb = (t & 3) * 4;        // 0,4,8,12
            int grow = row0 + r;
            float4 v = make_float4(0.f, 0.f, 0.f, 0.f);
            if (grow < n) v = *(const float4*)&X[(size_t)grow * C + k0 + kb];
            Xs[kb + 0][r] = v.x; Xs[kb + 1][r] = v.y;
            Xs[kb + 2][r] = v.z; Xs[kb + 3][r] = v.w;
        }
        // W tile: 16 x 128 -> 512 float4, 2 per thread
#pragma unroll
        for (int i = 0; i < 2; i++) {
            int t  = tx + i * 256;
            int kk = t >> 5;
            int c4 = (t & 31) * 4;
            float4 w = *(const float4*)&W[(k0 + kk) * C + c4];
            Ws[kk][c4 + 0] = w.x; Ws[kk][c4 + 1] = w.y;
            Ws[kk][c4 + 2] = w.z; Ws[kk][c4 + 3] = w.w;
        }
        __syncthreads();
#pragma unroll
        for (int kk = 0; kk < 16; kk++) {
            float4 a0 = *(const float4*)&Xs[kk][rg * 8];
            float4 a1 = *(const float4*)&Xs[kk][rg * 8 + 4];
            ulonglong2 b01 = *(const ulonglong2*)&Ws[kk][cg * 8];       // cols pair {0,1},{2,3}
            ulonglong2 b23 = *(const ulonglong2*)&Ws[kk][cg * 8 + 4];   // cols pair {4,5},{6,7}
            float av[8] = {a0.x, a0.y, a0.z, a0.w, a1.x, a1.y, a1.z, a1.w};
#pragma unroll
            for (int i = 0; i < 8; i++) {
                unsigned long long ad = dup2(av[i]);
                acc[i][0] = ffma2(ad, b01.x, acc[i][0]);
                acc[i][1] = ffma2(ad, b01.y, acc[i][1]);
                acc[i][2] = ffma2(ad, b23.x, acc[i][2]);
                acc[i][3] = ffma2(ad, b23.y, acc[i][3]);
            }
        }
        __syncthreads();
    }
#pragma unroll
    for (int i = 0; i < 8; i++) {
        int grow = row0 + rg * 8 + i;
        if (grow < n) {
            float2 c0 = unpack2(acc[i][0]);
            float2 c1 = unpack2(acc[i][1]);
            float2 c2 = unpack2(acc[i][2]);
            float2 c3 = unpack2(acc[i][3]);
            *(float4*)&g_xw[(size_t)grow * C + cg * 8]     = make_float4(c0.x, c0.y, c1.x, c1.y);
            *(float4*)&g_xw[(size_t)grow * C + cg * 8 + 4] = make_float4(c2.x, c2.y, c3.x, c3.y);
        }
    }
}

// ---------------- aggregation: dst[i] = relu(sum_in nm*xw[src] + dinv^2*xw[i] + b) ----------------
// one warp per node; lane owns channels lane*4..lane*4+3. dst: 0 = g_hA, 1 = g_hB
__global__ void __launch_bounds__(256) k_agg(const float* __restrict__ bias, int dst, int n) {
    const float4* __restrict__ xw = (const float4*)g_xw;
    float4* __restrict__ out = dst ? (float4*)g_hB : (float4*)g_hA;
    int warp = (blockIdx.x * blockDim.x + threadIdx.x) >> 5;
    int lane = threadIdx.x & 31;
    if (warp >= n) return;
    float dv = g_dinv[warp];
    float sw = dv * dv;
    float4 v = xw[(size_t)warp * 32 + lane];
    float a0 = sw * v.x, a1 = sw * v.y, a2 = sw * v.z, a3 = sw * v.w;
    int s = g_off[warp], e = g_off[warp + 1];
    for (int j = s; j < e; j++) {
        int2 ed = g_edat[j];
        float nm = __int_as_float(ed.y);
        float4 u = xw[(size_t)ed.x * 32 + lane];
        a0 = fmaf(nm, u.x, a0);
        a1 = fmaf(nm, u.y, a1);
        a2 = fmaf(nm, u.z, a2);
        a3 = fmaf(nm, u.w, a3);
    }
    float4 bb = ((const float4*)bias)[lane];
    float4 r;
    r.x = fmaxf(a0 + bb.x, 0.f);
    r.y = fmaxf(a1 + bb.y, 0.f);
    r.z = fmaxf(a2 + bb.z, 0.f);
    r.w = fmaxf(a3 + bb.w, 0.f);
    out[(size_t)warp * 32 + lane] = r;
}

// ---------------- fused layer-3 aggregation + linear head ----------------
// out[i] = relu(agg)[i,:] . lin_w + lin_b  (never materializes h3)
__global__ void __launch_bounds__(256) k_agg_head(const float* __restrict__ bias,
                                                  const float* __restrict__ lw,
                                                  const float* __restrict__ lb,
                                                  float* __restrict__ outp, int n) {
    const float4* __restrict__ xw = (const float4*)g_xw;
    int warp = (blockIdx.x * blockDim.x + threadIdx.x) >> 5;
    int lane = threadIdx.x & 31;
    if (warp >= n) return;
    float dv = g_dinv[warp];
    float sw = dv * dv;
    float4 v = xw[(size_t)warp * 32 + lane];
    float a0 = sw * v.x, a1 = sw * v.y, a2 = sw * v.z, a3 = sw * v.w;
    int s = g_off[warp], e = g_off[warp + 1];
    for (int j = s; j < e; j++) {
        int2 ed = g_edat[j];
        float nm = __int_as_float(ed.y);
        float4 u = xw[(size_t)ed.x * 32 + lane];
        a0 = fmaf(nm, u.x, a0);
        a1 = fmaf(nm, u.y, a1);
        a2 = fmaf(nm, u.z, a2);
        a3 = fmaf(nm, u.w, a3);
    }
    float4 bb = ((const float4*)bias)[lane];
    float4 w  = ((const float4*)lw)[lane];
    float sdot = fmaxf(a0 + bb.x, 0.f) * w.x
               + fmaxf(a1 + bb.y, 0.f) * w.y
               + fmaxf(a2 + bb.z, 0.f) * w.z
               + fmaxf(a3 + bb.w, 0.f) * w.w;
#pragma unroll
    for (int o = 16; o; o >>= 1) sdot += __shfl_down_sync(0xffffffffu, sdot, o);
    if (lane == 0) outp[warp] = sdot + lb[0];
}

// ---------------- host launch (kernel launches ONLY) ----------------
extern "C" void kernel_launch(void* const* d_in, const int* in_sizes, int n_in,
                              void* d_out, int out_size) {
    const float* x  = (const float*)d_in[0];
    const void*  ei = d_in[1];
    const float* ea = (const float*)d_in[2];
    const float* W1 = (const float*)d_in[3];
    const float* b1 = (const float*)d_in[4];
    const float* W2 = (const float*)d_in[5];
    const float* b2 = (const float*)d_in[6];
    const float* W3 = (const float*)d_in[7];
    const float* b3 = (const float*)d_in[8];
    const float* lw = (const float*)d_in[9];
    const float* lb = (const float*)d_in[10];
    float* outp = (float*)d_out;

    const int n = in_sizes[0] / C;
    const int e = in_sizes[2];

    const int nbN    = (n + 255) / 256;
    const int nbE    = (e + 255) / 256;
    const int nbScan = (n + 1023) / 1024;
    const int nbDet  = (2 * e + 255) / 256;

    // ---- normalization + CSC build ----
    k_init   <<<nbN, 256>>>(n);
    k_detect <<<nbDet, 256>>>((const unsigned int*)ei, 2 * e);
    k_prep   <<<nbE, 256>>>(ei, ea, e, n);
    k_dinv   <<<nbN, 256>>>(n);
    k_scan1  <<<nbScan, 1024>>>(n);
    k_scan2  <<<1, 1024>>>(nbScan);
    k_scan3  <<<nbScan, 1024>>>(n, e);
    k_scatter<<<nbE, 256>>>(ei, ea, e, n);
    k_fixend <<<1, 32>>>(n);

    const int nbG = (n + 127) / 128;
    const int nbW = (n * 32 + 255) / 256;

    // ---- layer 1 ----
    k_gemm<<<nbG, 256>>>(x, W1, 0, n);
    k_agg <<<nbW, 256>>>(b1, 0, n);            // -> hA
    // ---- layer 2 ----
    k_gemm<<<nbG, 256>>>(x, W2, 1, n);         // src = hA
    k_agg <<<nbW, 256>>>(b2, 1, n);            // -> hB
    // ---- layer 3 + head (fused) ----
    k_gemm<<<nbG, 256>>>(x, W3, 2, n);         // src = hB
    k_agg_head<<<nbW, 256>>>(b3, lw, lb, outp, n);
}

// round 9
// speedup vs baseline: 1.4286x; 1.3907x over previous
#include <cuda_runtime.h>
#include <cuda_fp16.h>
#include <stdint.h>

#define MAXN 100000
#define MAXE 1600000
#define C    128

// ---------------- static device scratch ----------------
__device__ float  g_deg[MAXN];
__device__ float  g_dinv[MAXN];
__device__ int    g_count[MAXN];
__device__ int    g_off[MAXN + 1];
__device__ int    g_cursor[MAXN];
__device__ int    g_bsum[1024];
__device__ int    g_bsumscan[1024];
__device__ int2   g_edat[MAXE];              // (src, norm-bits) grouped by dst
__device__ __half g_xw_h[(size_t)MAXN * C];  // GEMM output, fp16 (halves agg gather BW)
__device__ float  g_hA[(size_t)MAXN * C];
__device__ float  g_hB[(size_t)MAXN * C];
__device__ int    g_idx32;

// ---------------- dtype detection ----------------
// int64 indices (< 2^31): every odd 32-bit word is 0. int32: OR of odd words != 0.
__global__ void k_detect(const unsigned int* __restrict__ w, int nwords) {
    int i = blockIdx.x * blockDim.x + threadIdx.x;
    unsigned int v = (i < nwords && (i & 1)) ? w[i] : 0u;
#pragma unroll
    for (int o = 16; o; o >>= 1) v |= __shfl_down_sync(0xffffffffu, v, o);
    if ((threadIdx.x & 31) == 0 && v) atomicOr(&g_idx32, 1);
}
__device__ __forceinline__ void load_edge(const void* ei, int i, int e, int& r, int& c) {
    if (g_idx32) {
        const int* p = (const int*)ei;
        r = p[i]; c = p[e + i];
    } else {
        const long long* p = (const long long*)ei;
        r = (int)p[i]; c = (int)p[e + i];
    }
}

// ---------------- precompute ----------------
__global__ void k_init(int n) {
    int i = blockIdx.x * blockDim.x + threadIdx.x;
    if (i < n) { g_deg[i] = 1.0f; g_count[i] = 0; }
    if (i == 0) g_idx32 = 0;
}
__global__ void k_prep(const void* __restrict__ ei, const float* __restrict__ ea, int e, int n) {
    int i = blockIdx.x * blockDim.x + threadIdx.x;
    if (i >= e) return;
    int r, c;
    load_edge(ei, i, e, r, c);
    if ((unsigned)r >= (unsigned)n || (unsigned)c >= (unsigned)n) return;
    atomicAdd(&g_deg[c], ea[i]);
    atomicAdd(&g_count[c], 1);
}
__global__ void k_dinv(int n) {
    int i = blockIdx.x * blockDim.x + threadIdx.x;
    if (i < n) g_dinv[i] = rsqrtf(g_deg[i]);
}
__global__ void k_scan1(int n) {
    __shared__ int sh[1024];
    int gid = blockIdx.x * 1024 + threadIdx.x;
    int v = (gid < n) ? g_count[gid] : 0;
    sh[threadIdx.x] = v;
    __syncthreads();
    for (int off = 1; off < 1024; off <<= 1) {
        int t = 0;
        if ((int)threadIdx.x >= off) t = sh[threadIdx.x - off];
        __syncthreads();
        sh[threadIdx.x] += t;
        __syncthreads();
    }
    if (gid < n) g_off[gid] = sh[threadIdx.x] - v;
    if (threadIdx.x == 1023) g_bsum[blockIdx.x] = sh[1023];
}
__global__ void k_scan2(int nb) {
    __shared__ int sh[1024];
    int v = ((int)threadIdx.x < nb) ? g_bsum[threadIdx.x] : 0;
    sh[threadIdx.x] = v;
    __syncthreads();
    for (int off = 1; off < 1024; off <<= 1) {
        int t = 0;
        if ((int)threadIdx.x >= off) t = sh[threadIdx.x - off];
        __syncthreads();
        sh[threadIdx.x] += t;
        __syncthreads();
    }
    if ((int)threadIdx.x < nb) g_bsumscan[threadIdx.x] = sh[threadIdx.x] - v;
}
__global__ void k_scan3(int n, int ecnt) {
    int gid = blockIdx.x * 1024 + threadIdx.x;
    if (gid < n) {
        int v = g_off[gid] + g_bsumscan[blockIdx.x];
        g_off[gid]    = v;
        g_cursor[gid] = v;
    }
    if (gid == 0) g_off[n] = ecnt;
}
__global__ void k_scatter(const void* __restrict__ ei, const float* __restrict__ ea, int e, int n) {
    int i = blockIdx.x * blockDim.x + threadIdx.x;
    if (i >= e) return;
    int r, c;
    load_edge(ei, i, e, r, c);
    if ((unsigned)r >= (unsigned)n || (unsigned)c >= (unsigned)n) return;
    float nm = g_dinv[r] * ea[i] * g_dinv[c];
    int pos = atomicAdd(&g_cursor[c], 1);
    g_edat[pos] = make_int2(r, __float_as_int(nm));
}
__global__ void k_fixend(int n) {
    if (blockIdx.x == 0 && threadIdx.x == 0) g_off[n] = g_cursor[n - 1];
}

// ================= tf32 mma.sync GEMM: g_xw_h = (src @ W) as fp16 =================
__device__ __forceinline__ uint32_t to_tf32(float x) {
    uint32_t r;
    asm("cvt.rna.tf32.f32 %0, %1;" : "=r"(r) : "f"(x));
    return r;
}
__device__ __forceinline__ void mma_tf32(float* d, const uint32_t* a, const uint32_t* b) {
    asm volatile(
        "mma.sync.aligned.m16n8k8.row.col.f32.tf32.tf32.f32 "
        "{%0,%1,%2,%3}, {%4,%5,%6,%7}, {%8,%9}, {%0,%1,%2,%3};"
        : "+f"(d[0]), "+f"(d[1]), "+f"(d[2]), "+f"(d[3])
        : "r"(a[0]), "r"(a[1]), "r"(a[2]), "r"(a[3]), "r"(b[0]), "r"(b[1]));
}

#define PX 132   // smem pitch (words): bank = 4*k + col  -> conflict-free frags

// 128x128 CTA tile, 8 warps: warp (w&3) -> 32-row band, (w>>2) -> 64-col band.
// smem staged per K-chunk of 32: Xs[k][row], Ws[k][n], both tf32.
// src: 0 = harness x, 1 = g_hA, 2 = g_hB
__global__ void __launch_bounds__(256) k_gemm_mma(const float* __restrict__ Xext,
                                                  const float* __restrict__ W,
                                                  int src, int n) {
    const float* __restrict__ X = (src == 0) ? Xext : (src == 1 ? g_hA : g_hB);

    __shared__ uint32_t Xs[32 * PX];
    __shared__ uint32_t Ws[32 * PX];

    const int tid  = threadIdx.x;
    const int wid  = tid >> 5;
    const int lane = tid & 31;
    const int g    = lane >> 2;    // groupID
    const int tg   = lane & 3;     // threadID-in-group
    const int row0 = blockIdx.x * 128;
    const int mrow = (wid & 3) * 32;
    const int ncol = (wid >> 2) * 64;

    float acc[2][8][4];
#pragma unroll
    for (int i = 0; i < 2; i++)
#pragma unroll
        for (int j = 0; j < 8; j++)
#pragma unroll
            for (int t = 0; t < 4; t++) acc[i][j][t] = 0.0f;

    const int xrow  = tid >> 1;        // 0..127
    const int xhalf = tid & 1;         // 16-float half of the 32-float k-chunk row
    const int wkrow = tid >> 3;        // 0..31
    const int wseg  = tid & 7;         // 16-col segment

    for (int kc = 0; kc < 4; kc++) {
        // ---- stage X chunk: Xs[k][row] (tf32) ----
        {
            int grow = row0 + xrow;
            const float* xp = X + (size_t)grow * C + kc * 32 + xhalf * 16;
#pragma unroll
            for (int q = 0; q < 4; q++) {
                float4 v = (grow < n) ? *(const float4*)(xp + q * 4)
                                      : make_float4(0.f, 0.f, 0.f, 0.f);
                int c0 = xhalf * 16 + q * 4;
                Xs[(c0 + 0) * PX + xrow] = to_tf32(v.x);
                Xs[(c0 + 1) * PX + xrow] = to_tf32(v.y);
                Xs[(c0 + 2) * PX + xrow] = to_tf32(v.z);
                Xs[(c0 + 3) * PX + xrow] = to_tf32(v.w);
            }
        }
        // ---- stage W chunk: Ws[k][n] (tf32), vectorized stores ----
        {
            const float* wp = W + (size_t)(kc * 32 + wkrow) * C + wseg * 16;
#pragma unroll
            for (int q = 0; q < 4; q++) {
                float4 v = *(const float4*)(wp + q * 4);
                uint4 u = make_uint4(to_tf32(v.x), to_tf32(v.y), to_tf32(v.z), to_tf32(v.w));
                *(uint4*)&Ws[wkrow * PX + wseg * 16 + q * 4] = u;
            }
        }
        __syncthreads();

        // ---- 4 k-steps of 8 ----
#pragma unroll
        for (int s = 0; s < 4; s++) {
            const int ks = s * 8;
            uint32_t af[2][4];
#pragma unroll
            for (int i = 0; i < 2; i++) {
                int arow = mrow + i * 16 + g;
                af[i][0] = Xs[(ks + tg) * PX + arow];
                af[i][1] = Xs[(ks + tg) * PX + arow + 8];
                af[i][2] = Xs[(ks + tg + 4) * PX + arow];
                af[i][3] = Xs[(ks + tg + 4) * PX + arow + 8];
            }
#pragma unroll
            for (int j = 0; j < 8; j++) {
                uint32_t bf[2];
                int bcol = ncol + j * 8 + g;
                bf[0] = Ws[(ks + tg) * PX + bcol];
                bf[1] = Ws[(ks + tg + 4) * PX + bcol];
                mma_tf32(acc[0][j], af[0], bf);
                mma_tf32(acc[1][j], af[1], bf);
            }
        }
        __syncthreads();
    }

    // ---- epilogue: fp32 acc -> fp16 g_xw_h ----
#pragma unroll
    for (int i = 0; i < 2; i++) {
        int r0 = row0 + mrow + i * 16 + g;
        int r1 = r0 + 8;
#pragma unroll
        for (int j = 0; j < 8; j++) {
            int cc = ncol + j * 8 + 2 * tg;
            if (r0 < n) {
                __half2 h = __floats2half2_rn(acc[i][j][0], acc[i][j][1]);
                *(__half2*)(g_xw_h + (size_t)r0 * C + cc) = h;
            }
            if (r1 < n) {
                __half2 h = __floats2half2_rn(acc[i][j][2], acc[i][j][3]);
                *(__half2*)(g_xw_h + (size_t)r1 * C + cc) = h;
            }
        }
    }
}

// ---------------- aggregation (fp16 gathers): dst[i] = relu(sum nm*xw[src] + dinv^2*xw[i] + b)
__global__ void __launch_bounds__(256) k_agg(const float* __restrict__ bias, int dst, int n) {
    float4* __restrict__ out = dst ? (float4*)g_hB : (float4*)g_hA;
    int warp = (blockIdx.x * blockDim.x + threadIdx.x) >> 5;
    int lane = threadIdx.x & 31;
    if (warp >= n) return;
    float dv = g_dinv[warp];
    float sw = dv * dv;
    uint2 su = *(const uint2*)(g_xw_h + (size_t)warp * C + lane * 4);
    float2 s0 = __half22float2(*(__half2*)&su.x);
    float2 s1 = __half22float2(*(__half2*)&su.y);
    float a0 = sw * s0.x, a1 = sw * s0.y, a2 = sw * s1.x, a3 = sw * s1.y;
    int s = g_off[warp], e = g_off[warp + 1];
    for (int j = s; j < e; j++) {
        int2 ed = g_edat[j];
        float nm = __int_as_float(ed.y);
        uint2 u = *(const uint2*)(g_xw_h + (size_t)ed.x * C + lane * 4);   // 256B/edge
        float2 p0 = __half22float2(*(__half2*)&u.x);
        float2 p1 = __half22float2(*(__half2*)&u.y);
        a0 = fmaf(nm, p0.x, a0);
        a1 = fmaf(nm, p0.y, a1);
        a2 = fmaf(nm, p1.x, a2);
        a3 = fmaf(nm, p1.y, a3);
    }
    float4 bb = ((const float4*)bias)[lane];
    float4 r;
    r.x = fmaxf(a0 + bb.x, 0.f);
    r.y = fmaxf(a1 + bb.y, 0.f);
    r.z = fmaxf(a2 + bb.z, 0.f);
    r.w = fmaxf(a3 + bb.w, 0.f);
    out[(size_t)warp * 32 + lane] = r;
}

// ---------------- fused layer-3 aggregation + linear head ----------------
__global__ void __launch_bounds__(256) k_agg_head(const float* __restrict__ bias,
                                                  const float* __restrict__ lw,
                                                  const float* __restrict__ lb,
                                                  float* __restrict__ outp, int n) {
    int warp = (blockIdx.x * blockDim.x + threadIdx.x) >> 5;
    int lane = threadIdx.x & 31;
    if (warp >= n) return;
    float dv = g_dinv[warp];
    float sw = dv * dv;
    uint2 su = *(const uint2*)(g_xw_h + (size_t)warp * C + lane * 4);
    float2 s0 = __half22float2(*(__half2*)&su.x);
    float2 s1 = __half22float2(*(__half2*)&su.y);
    float a0 = sw * s0.x, a1 = sw * s0.y, a2 = sw * s1.x, a3 = sw * s1.y;
    int s = g_off[warp], e = g_off[warp + 1];
    for (int j = s; j < e; j++) {
        int2 ed = g_edat[j];
        float nm = __int_as_float(ed.y);
        uint2 u = *(const uint2*)(g_xw_h + (size_t)ed.x * C + lane * 4);
        float2 p0 = __half22float2(*(__half2*)&u.x);
        float2 p1 = __half22float2(*(__half2*)&u.y);
        a0 = fmaf(nm, p0.x, a0);
        a1 = fmaf(nm, p0.y, a1);
        a2 = fmaf(nm, p1.x, a2);
        a3 = fmaf(nm, p1.y, a3);
    }
    float4 bb = ((const float4*)bias)[lane];
    float4 w  = ((const float4*)lw)[lane];
    float sdot = fmaxf(a0 + bb.x, 0.f) * w.x
               + fmaxf(a1 + bb.y, 0.f) * w.y
               + fmaxf(a2 + bb.z, 0.f) * w.z
               + fmaxf(a3 + bb.w, 0.f) * w.w;
#pragma unroll
    for (int o = 16; o; o >>= 1) sdot += __shfl_down_sync(0xffffffffu, sdot, o);
    if (lane == 0) outp[warp] = sdot + lb[0];
}

// ---------------- host launch (kernel launches ONLY) ----------------
extern "C" void kernel_launch(void* const* d_in, const int* in_sizes, int n_in,
                              void* d_out, int out_size) {
    const float* x  = (const float*)d_in[0];
    const void*  ei = d_in[1];
    const float* ea = (const float*)d_in[2];
    const float* W1 = (const float*)d_in[3];
    const float* b1 = (const float*)d_in[4];
    const float* W2 = (const float*)d_in[5];
    const float* b2 = (const float*)d_in[6];
    const float* W3 = (const float*)d_in[7];
    const float* b3 = (const float*)d_in[8];
    const float* lw = (const float*)d_in[9];
    const float* lb = (const float*)d_in[10];
    float* outp = (float*)d_out;

    const int n = in_sizes[0] / C;
    const int e = in_sizes[2];

    const int nbN    = (n + 255) / 256;
    const int nbE    = (e + 255) / 256;
    const int nbScan = (n + 1023) / 1024;
    const int nbDet  = (2 * e + 255) / 256;

    // ---- normalization + CSC build ----
    k_init   <<<nbN, 256>>>(n);
    k_detect <<<nbDet, 256>>>((const unsigned int*)ei, 2 * e);
    k_prep   <<<nbE, 256>>>(ei, ea, e, n);
    k_dinv   <<<nbN, 256>>>(n);
    k_scan1  <<<nbScan, 1024>>>(n);
    k_scan2  <<<1, 1024>>>(nbScan);
    k_scan3  <<<nbScan, 1024>>>(n, e);
    k_scatter<<<nbE, 256>>>(ei, ea, e, n);
    k_fixend <<<1, 32>>>(n);

    const int nbG = (n + 127) / 128;
    const int nbW = (n * 32 + 255) / 256;

    // ---- layer 1 ----
    k_gemm_mma<<<nbG, 256>>>(x, W1, 0, n);
    k_agg     <<<nbW, 256>>>(b1, 0, n);         // -> hA
    // ---- layer 2 ----
    k_gemm_mma<<<nbG, 256>>>(x, W2, 1, n);      // src = hA
    k_agg     <<<nbW, 256>>>(b2, 1, n);         // -> hB
    // ---- layer 3 + head (fused) ----
    k_gemm_mma<<<nbG, 256>>>(x, W3, 2, n);      // src = hB
    k_agg_head<<<nbW, 256>>>(b3, lw, lb, outp, n);
}

// round 10
// speedup vs baseline: 1.4606x; 1.0224x over previous
#include <cuda_runtime.h>
#include <cuda_fp16.h>
#include <stdint.h>

#define MAXN 100000
#define MAXE 1600000
#define C    128

// ---------------- static device scratch ----------------
__device__ float  g_deg[MAXN];
__device__ float  g_dinv[MAXN];
__device__ int    g_count[MAXN];
__device__ int    g_off[MAXN + 1];
__device__ int    g_cursor[MAXN];
__device__ int    g_bsum[1024];
__device__ int    g_bsumscan[1024];
__device__ int2   g_edat[MAXE];              // (src, norm-bits) grouped by dst
__device__ __half g_xw_h[(size_t)MAXN * C];  // GEMM output, fp16
__device__ float  g_hA[(size_t)MAXN * C];
__device__ float  g_hB[(size_t)MAXN * C];
__device__ int    g_idx32 = 0;               // monotonic: 0 = int64 idx, 1 = int32 idx

// ---------------- fused init + dtype detect ----------------
// int64 indices (< 2^31): every odd 32-bit word is 0. int32: OR of odd words != 0.
// g_idx32 is statically 0 and only ever OR'ed to 1 -> deterministic across replays.
__global__ void k_initdetect(const unsigned int* __restrict__ w, int nwords, int n) {
    int i = blockIdx.x * blockDim.x + threadIdx.x;
    if (i < n) { g_deg[i] = 1.0f; g_count[i] = 0; }
    unsigned int v = (i < nwords && (i & 1)) ? w[i] : 0u;
#pragma unroll
    for (int o = 16; o; o >>= 1) v |= __shfl_down_sync(0xffffffffu, v, o);
    if ((threadIdx.x & 31) == 0 && v) atomicOr(&g_idx32, 1);
}
__device__ __forceinline__ void load_edge(const void* ei, int i, int e, int& r, int& c) {
    if (g_idx32) {
        const int* p = (const int*)ei;
        r = p[i]; c = p[e + i];
    } else {
        const long long* p = (const long long*)ei;
        r = (int)p[i]; c = (int)p[e + i];
    }
}

// ---------------- precompute ----------------
__global__ void k_prep(const void* __restrict__ ei, const float* __restrict__ ea, int e, int n) {
    int i = blockIdx.x * blockDim.x + threadIdx.x;
    if (i >= e) return;
    int r, c;
    load_edge(ei, i, e, r, c);
    if ((unsigned)r >= (unsigned)n || (unsigned)c >= (unsigned)n) return;
    atomicAdd(&g_deg[c], ea[i]);
    atomicAdd(&g_count[c], 1);
}

// scan1 + dinv fused (both depend only on k_prep)
__global__ void k_scan1(int n) {
    __shared__ int sh[1024];
    int gid = blockIdx.x * 1024 + threadIdx.x;
    int v = (gid < n) ? g_count[gid] : 0;
    if (gid < n) g_dinv[gid] = rsqrtf(g_deg[gid]);   // deg >= 1 always
    sh[threadIdx.x] = v;
    __syncthreads();
    for (int off = 1; off < 1024; off <<= 1) {
        int t = 0;
        if ((int)threadIdx.x >= off) t = sh[threadIdx.x - off];
        __syncthreads();
        sh[threadIdx.x] += t;
        __syncthreads();
    }
    if (gid < n) g_off[gid] = sh[threadIdx.x] - v;
    if (threadIdx.x == 1023) g_bsum[blockIdx.x] = sh[1023];
}
__global__ void k_scan2(int nb) {
    __shared__ int sh[1024];
    int v = ((int)threadIdx.x < nb) ? g_bsum[threadIdx.x] : 0;
    sh[threadIdx.x] = v;
    __syncthreads();
    for (int off = 1; off < 1024; off <<= 1) {
        int t = 0;
        if ((int)threadIdx.x >= off) t = sh[threadIdx.x - off];
        __syncthreads();
        sh[threadIdx.x] += t;
        __syncthreads();
    }
    if ((int)threadIdx.x < nb) g_bsumscan[threadIdx.x] = sh[threadIdx.x] - v;
}
__global__ void k_scan3(int n) {
    int gid = blockIdx.x * 1024 + threadIdx.x;
    if (gid < n) {
        int v = g_off[gid] + g_bsumscan[blockIdx.x];
        g_off[gid]    = v;
        g_cursor[gid] = v;
    }
}
__global__ void k_scatter(const void* __restrict__ ei, const float* __restrict__ ea, int e, int n) {
    int i = blockIdx.x * blockDim.x + threadIdx.x;
    if (i >= e) return;
    int r, c;
    load_edge(ei, i, e, r, c);
    if ((unsigned)r >= (unsigned)n || (unsigned)c >= (unsigned)n) return;
    float nm = g_dinv[r] * ea[i] * g_dinv[c];
    int pos = atomicAdd(&g_cursor[c], 1);
    g_edat[pos] = make_int2(r, __float_as_int(nm));
}
// NOTE: after k_scatter, g_cursor[c] == end of segment c  (used by agg; no fixend kernel)

// ================= tf32 mma.sync GEMM (software-pipelined): g_xw_h = (src @ W) as fp16 =================
__device__ __forceinline__ uint32_t to_tf32(float x) {
    uint32_t r;
    asm("cvt.rna.tf32.f32 %0, %1;" : "=r"(r) : "f"(x));
    return r;
}
__device__ __forceinline__ void mma_tf32(float* d, const uint32_t* a, const uint32_t* b) {
    asm volatile(
        "mma.sync.aligned.m16n8k8.row.col.f32.tf32.tf32.f32 "
        "{%0,%1,%2,%3}, {%4,%5,%6,%7}, {%8,%9}, {%0,%1,%2,%3};"
        : "+f"(d[0]), "+f"(d[1]), "+f"(d[2]), "+f"(d[3])
        : "r"(a[0]), "r"(a[1]), "r"(a[2]), "r"(a[3]), "r"(b[0]), "r"(b[1]));
}

#define PX 132   // smem pitch (words)

// 128x128 CTA tile, 8 warps: warp (w&3) -> 32-row band, (w>>2) -> 64-col band.
// Register-prefetch of next K-chunk overlaps gmem latency with MMA compute.
// src: 0 = harness x, 1 = g_hA, 2 = g_hB
__global__ void __launch_bounds__(256, 2) k_gemm_mma(const float* __restrict__ Xext,
                                                     const float* __restrict__ W,
                                                     int src, int n) {
    const float* __restrict__ X = (src == 0) ? Xext : (src == 1 ? g_hA : g_hB);

    __shared__ uint32_t Xs[32 * PX];
    __shared__ uint32_t Ws[32 * PX];

    const int tid  = threadIdx.x;
    const int wid  = tid >> 5;
    const int lane = tid & 31;
    const int g    = lane >> 2;
    const int tg   = lane & 3;
    const int row0 = blockIdx.x * 128;
    const int mrow = (wid & 3) * 32;
    const int ncol = (wid >> 2) * 64;

    const int xrow  = tid >> 1;        // 0..127
    const int xhalf = tid & 1;
    const int wkrow = tid >> 3;        // 0..31
    const int wseg  = tid & 7;

    const int  xgrow = row0 + xrow;
    const bool xok   = (xgrow < n);
    const float* xbase = X + (size_t)xgrow * C + xhalf * 16;
    const float* wbase = W + (size_t)wkrow * C + wseg * 16;

    float acc[2][8][4];
#pragma unroll
    for (int i = 0; i < 2; i++)
#pragma unroll
        for (int j = 0; j < 8; j++)
#pragma unroll
            for (int t = 0; t < 4; t++) acc[i][j][t] = 0.0f;

    float4 xv[4], wv[4];
    // ---- load chunk 0 ----
#pragma unroll
    for (int q = 0; q < 4; q++)
        xv[q] = xok ? *(const float4*)(xbase + q * 4) : make_float4(0.f, 0.f, 0.f, 0.f);
#pragma unroll
    for (int q = 0; q < 4; q++)
        wv[q] = *(const float4*)(wbase + q * 4);
    // ---- store chunk 0 ----
#pragma unroll
    for (int q = 0; q < 4; q++) {
        int c0 = xhalf * 16 + q * 4;
        float f[4] = {xv[q].x, xv[q].y, xv[q].z, xv[q].w};
#pragma unroll
        for (int t = 0; t < 4; t++) Xs[(c0 + t) * PX + xrow] = to_tf32(f[t]);
        *(uint4*)&Ws[wkrow * PX + wseg * 16 + q * 4] =
            make_uint4(to_tf32(wv[q].x), to_tf32(wv[q].y), to_tf32(wv[q].z), to_tf32(wv[q].w));
    }
    __syncthreads();

#pragma unroll
    for (int kc = 0; kc < 4; kc++) {
        // ---- prefetch chunk kc+1 into registers (overlaps with MMA below) ----
        if (kc < 3) {
#pragma unroll
            for (int q = 0; q < 4; q++)
                xv[q] = xok ? *(const float4*)(xbase + (kc + 1) * 32 + q * 4)
                            : make_float4(0.f, 0.f, 0.f, 0.f);
#pragma unroll
            for (int q = 0; q < 4; q++)
                wv[q] = *(const float4*)(wbase + (size_t)(kc + 1) * 32 * C + q * 4);
        }
        // ---- compute chunk kc ----
#pragma unroll
        for (int s = 0; s < 4; s++) {
            const int ks = s * 8;
            uint32_t af[2][4];
#pragma unroll
            for (int i = 0; i < 2; i++) {
                int arow = mrow + i * 16 + g;
                af[i][0] = Xs[(ks + tg) * PX + arow];
                af[i][1] = Xs[(ks + tg) * PX + arow + 8];
                af[i][2] = Xs[(ks + tg + 4) * PX + arow];
                af[i][3] = Xs[(ks + tg + 4) * PX + arow + 8];
            }
#pragma unroll
            for (int j = 0; j < 8; j++) {
                uint32_t bf[2];
                int bcol = ncol + j * 8 + g;
                bf[0] = Ws[(ks + tg) * PX + bcol];
                bf[1] = Ws[(ks + tg + 4) * PX + bcol];
                mma_tf32(acc[0][j], af[0], bf);
                mma_tf32(acc[1][j], af[1], bf);
            }
        }
        __syncthreads();
        // ---- store prefetched chunk ----
        if (kc < 3) {
#pragma unroll
            for (int q = 0; q < 4; q++) {
                int c0 = xhalf * 16 + q * 4;
                float f[4] = {xv[q].x, xv[q].y, xv[q].z, xv[q].w};
#pragma unroll
                for (int t = 0; t < 4; t++) Xs[(c0 + t) * PX + xrow] = to_tf32(f[t]);
                *(uint4*)&Ws[wkrow * PX + wseg * 16 + q * 4] =
                    make_uint4(to_tf32(wv[q].x), to_tf32(wv[q].y), to_tf32(wv[q].z), to_tf32(wv[q].w));
            }
            __syncthreads();
        }
    }

    // ---- epilogue: fp32 acc -> fp16 g_xw_h ----
#pragma unroll
    for (int i = 0; i < 2; i++) {
        int r0 = row0 + mrow + i * 16 + g;
        int r1 = r0 + 8;
#pragma unroll
        for (int j = 0; j < 8; j++) {
            int cc = ncol + j * 8 + 2 * tg;
            if (r0 < n) {
                __half2 h = __floats2half2_rn(acc[i][j][0], acc[i][j][1]);
                *(__half2*)(g_xw_h + (size_t)r0 * C + cc) = h;
            }
            if (r1 < n) {
                __half2 h = __floats2half2_rn(acc[i][j][2], acc[i][j][3]);
                *(__half2*)(g_xw_h + (size_t)r1 * C + cc) = h;
            }
        }
    }
}

// ---------------- aggregation (fp16 gathers): dst[i] = relu(sum nm*xw[src] + dinv^2*xw[i] + b)
__global__ void __launch_bounds__(256) k_agg(const float* __restrict__ bias, int dst, int n) {
    float4* __restrict__ out = dst ? (float4*)g_hB : (float4*)g_hA;
    int warp = (blockIdx.x * blockDim.x + threadIdx.x) >> 5;
    int lane = threadIdx.x & 31;
    if (warp >= n) return;
    float dv = g_dinv[warp];
    float sw = dv * dv;
    uint2 su = *(const uint2*)(g_xw_h + (size_t)warp * C + lane * 4);
    float2 s0 = __half22float2(*(__half2*)&su.x);
    float2 s1 = __half22float2(*(__half2*)&su.y);
    float a0 = sw * s0.x, a1 = sw * s0.y, a2 = sw * s1.x, a3 = sw * s1.y;
    int s = g_off[warp], e = g_cursor[warp];   // cursor == segment end post-scatter
    for (int j = s; j < e; j++) {
        int2 ed = g_edat[j];
        float nm = __int_as_float(ed.y);
        uint2 u = *(const uint2*)(g_xw_h + (size_t)ed.x * C + lane * 4);
        float2 p0 = __half22float2(*(__half2*)&u.x);
        float2 p1 = __half22float2(*(__half2*)&u.y);
        a0 = fmaf(nm, p0.x, a0);
        a1 = fmaf(nm, p0.y, a1);
        a2 = fmaf(nm, p1.x, a2);
        a3 = fmaf(nm, p1.y, a3);
    }
    float4 bb = ((const float4*)bias)[lane];
    float4 r;
    r.x = fmaxf(a0 + bb.x, 0.f);
    r.y = fmaxf(a1 + bb.y, 0.f);
    r.z = fmaxf(a2 + bb.z, 0.f);
    r.w = fmaxf(a3 + bb.w, 0.f);
    out[(size_t)warp * 32 + lane] = r;
}

// ---------------- fused layer-3 aggregation + linear head ----------------
__global__ void __launch_bounds__(256) k_agg_head(const float* __restrict__ bias,
                                                  const float* __restrict__ lw,
                                                  const float* __restrict__ lb,
                                                  float* __restrict__ outp, int n) {
    int warp = (blockIdx.x * blockDim.x + threadIdx.x) >> 5;
    int lane = threadIdx.x & 31;
    if (warp >= n) return;
    float dv = g_dinv[warp];
    float sw = dv * dv;
    uint2 su = *(const uint2*)(g_xw_h + (size_t)warp * C + lane * 4);
    float2 s0 = __half22float2(*(__half2*)&su.x);
    float2 s1 = __half22float2(*(__half2*)&su.y);
    float a0 = sw * s0.x, a1 = sw * s0.y, a2 = sw * s1.x, a3 = sw * s1.y;
    int s = g_off[warp], e = g_cursor[warp];
    for (int j = s; j < e; j++) {
        int2 ed = g_edat[j];
        float nm = __int_as_float(ed.y);
        uint2 u = *(const uint2*)(g_xw_h + (size_t)ed.x * C + lane * 4);
        float2 p0 = __half22float2(*(__half2*)&u.x);
        float2 p1 = __half22float2(*(__half2*)&u.y);
        a0 = fmaf(nm, p0.x, a0);
        a1 = fmaf(nm, p0.y, a1);
        a2 = fmaf(nm, p1.x, a2);
        a3 = fmaf(nm, p1.y, a3);
    }
    float4 bb = ((const float4*)bias)[lane];
    float4 w  = ((const float4*)lw)[lane];
    float sdot = fmaxf(a0 + bb.x, 0.f) * w.x
               + fmaxf(a1 + bb.y, 0.f) * w.y
               + fmaxf(a2 + bb.z, 0.f) * w.z
               + fmaxf(a3 + bb.w, 0.f) * w.w;
#pragma unroll
    for (int o = 16; o; o >>= 1) sdot += __shfl_down_sync(0xffffffffu, sdot, o);
    if (lane == 0) outp[warp] = sdot + lb[0];
}

// ---------------- host launch (kernel launches ONLY) ----------------
extern "C" void kernel_launch(void* const* d_in, const int* in_sizes, int n_in,
                              void* d_out, int out_size) {
    const float* x  = (const float*)d_in[0];
    const void*  ei = d_in[1];
    const float* ea = (const float*)d_in[2];
    const float* W1 = (const float*)d_in[3];
    const float* b1 = (const float*)d_in[4];
    const float* W2 = (const float*)d_in[5];
    const float* b2 = (const float*)d_in[6];
    const float* W3 = (const float*)d_in[7];
    const float* b3 = (const float*)d_in[8];
    const float* lw = (const float*)d_in[9];
    const float* lb = (const float*)d_in[10];
    float* outp = (float*)d_out;

    const int n = in_sizes[0] / C;
    const int e = in_sizes[2];

    const int nbE    = (e + 255) / 256;
    const int nbScan = (n + 1023) / 1024;
    const int nbDet  = (2 * e + 255) / 256;
    const int nbG    = (n + 127) / 128;
    const int nbW    = (n * 32 + 255) / 256;

    // launch #4 is k_gemm_mma -> ncu (-s 5 -c 1) captures the GEMM next profile
    k_initdetect<<<nbDet, 256>>>((const unsigned int*)ei, 2 * e, n);   // 1
    k_prep      <<<nbE, 256>>>(ei, ea, e, n);                          // 2
    k_scan1     <<<nbScan, 1024>>>(n);                                 // 3 (+dinv)
    k_gemm_mma  <<<nbG, 256>>>(x, W1, 0, n);                           // 4  <- profiled
    k_scan2     <<<1, 1024>>>(nbScan);                                 // 5
    k_scan3     <<<nbScan, 1024>>>(n);                                 // 6
    k_scatter   <<<nbE, 256>>>(ei, ea, e, n);                          // 7
    k_agg       <<<nbW, 256>>>(b1, 0, n);                              // 8  -> hA
    k_gemm_mma  <<<nbG, 256>>>(x, W2, 1, n);                           // 9  src = hA
    k_agg       <<<nbW, 256>>>(b2, 1, n);                              // 10 -> hB
    k_gemm_mma  <<<nbG, 256>>>(x, W3, 2, n);                           // 11 src = hB
    k_agg_head  <<<nbW, 256>>>(b3, lw, lb, outp, n);                   // 12
}

// round 11
// speedup vs baseline: 1.6228x; 1.1111x over previous
#include <cuda_runtime.h>
#include <cuda_fp16.h>
#include <stdint.h>

#define MAXN 100000
#define MAXE 1600000
#define C    128

// ---------------- static device scratch ----------------
__device__ float  g_deg[MAXN];
__device__ float  g_dinv[MAXN];
__device__ int    g_count[MAXN];
__device__ int    g_off[MAXN + 1];
__device__ int    g_cursor[MAXN];
__device__ int    g_bsum[1024];
__device__ int    g_bsumscan[1024];
__device__ int2   g_edat[MAXE];              // (src, norm-bits) grouped by dst
__device__ __half g_xw_h[(size_t)MAXN * C];  // GEMM output, fp16
__device__ float  g_hA[(size_t)MAXN * C];    // tf32-rounded activations
__device__ float  g_hB[(size_t)MAXN * C];    // tf32-rounded activations
__device__ float  g_xt[(size_t)MAXN * C];    // tf32-rounded copy of x
__device__ float  g_Wc[3 * C * C];           // tf32-rounded W1|W2|W3
__device__ int    g_idx32 = 0;               // monotonic: 0 = int64 idx, 1 = int32 idx

// ---------------- helpers ----------------
__device__ __forceinline__ uint32_t to_tf32(float x) {
    uint32_t r;
    asm("cvt.rna.tf32.f32 %0, %1;" : "=r"(r) : "f"(x));
    return r;
}
__device__ __forceinline__ float rnd_tf32(float x) { return __uint_as_float(to_tf32(x)); }

__device__ __forceinline__ void mma_tf32(float* d, const uint32_t* a, const uint32_t* b) {
    asm volatile(
        "mma.sync.aligned.m16n8k8.row.col.f32.tf32.tf32.f32 "
        "{%0,%1,%2,%3}, {%4,%5,%6,%7}, {%8,%9}, {%0,%1,%2,%3};"
        : "+f"(d[0]), "+f"(d[1]), "+f"(d[2]), "+f"(d[3])
        : "r"(a[0]), "r"(a[1]), "r"(a[2]), "r"(a[3]), "r"(b[0]), "r"(b[1]));
}
__device__ __forceinline__ uint32_t smem_u32(const void* p) {
    uint32_t a;
    asm("{ .reg .u64 t; cvta.to.shared.u64 t, %1; cvt.u32.u64 %0, t; }" : "=r"(a) : "l"(p));
    return a;
}
__device__ __forceinline__ void cp16(uint32_t dst, const void* src, int zf) {
    asm volatile("cp.async.cg.shared.global [%0], [%1], 16, %2;" :: "r"(dst), "l"(src), "r"(zf));
}
#define CP_COMMIT() asm volatile("cp.async.commit_group;" ::: "memory")
#define CP_WAIT(N)  asm volatile("cp.async.wait_group %0;" :: "n"(N) : "memory")

// ---------------- fused init + detect + tf32 pre-round ----------------
// idx dtype: int64 (<2^31) -> odd 32-bit words all 0; int32 -> OR != 0.
__global__ void k_initdetect(const unsigned int* __restrict__ w, int nwords, int n,
                             const float4* __restrict__ x4, int nx4,
                             const float* __restrict__ W1, const float* __restrict__ W2,
                             const float* __restrict__ W3) {
    int i = blockIdx.x * blockDim.x + threadIdx.x;
    if (i < n) { g_deg[i] = 1.0f; g_count[i] = 0; }
    unsigned int v = (i < nwords && (i & 1)) ? w[i] : 0u;
#pragma unroll
    for (int o = 16; o; o >>= 1) v |= __shfl_down_sync(0xffffffffu, v, o);
    if ((threadIdx.x & 31) == 0 && v) atomicOr(&g_idx32, 1);
    if (i < nx4) {
        float4 t = x4[i];
        t.x = rnd_tf32(t.x); t.y = rnd_tf32(t.y); t.z = rnd_tf32(t.z); t.w = rnd_tf32(t.w);
        ((float4*)g_xt)[i] = t;
    }
    if (i < C * C) {
        g_Wc[i]             = rnd_tf32(W1[i]);
        g_Wc[C * C + i]     = rnd_tf32(W2[i]);
        g_Wc[2 * C * C + i] = rnd_tf32(W3[i]);
    }
}
__device__ __forceinline__ void load_edge(const void* ei, int i, int e, int& r, int& c) {
    if (g_idx32) {
        const int* p = (const int*)ei;
        r = p[i]; c = p[e + i];
    } else {
        const long long* p = (const long long*)ei;
        r = (int)p[i]; c = (int)p[e + i];
    }
}

// ---------------- precompute ----------------
__global__ void k_prep(const void* __restrict__ ei, const float* __restrict__ ea, int e, int n) {
    int i = blockIdx.x * blockDim.x + threadIdx.x;
    if (i >= e) return;
    int r, c;
    load_edge(ei, i, e, r, c);
    if ((unsigned)r >= (unsigned)n || (unsigned)c >= (unsigned)n) return;
    atomicAdd(&g_deg[c], ea[i]);
    atomicAdd(&g_count[c], 1);
}
__global__ void k_scan1(int n) {
    __shared__ int sh[1024];
    int gid = blockIdx.x * 1024 + threadIdx.x;
    int v = (gid < n) ? g_count[gid] : 0;
    if (gid < n) g_dinv[gid] = rsqrtf(g_deg[gid]);
    sh[threadIdx.x] = v;
    __syncthreads();
    for (int off = 1; off < 1024; off <<= 1) {
        int t = 0;
        if ((int)threadIdx.x >= off) t = sh[threadIdx.x - off];
        __syncthreads();
        sh[threadIdx.x] += t;
        __syncthreads();
    }
    if (gid < n) g_off[gid] = sh[threadIdx.x] - v;
    if (threadIdx.x == 1023) g_bsum[blockIdx.x] = sh[1023];
}
__global__ void k_scan2(int nb) {
    __shared__ int sh[1024];
    int v = ((int)threadIdx.x < nb) ? g_bsum[threadIdx.x] : 0;
    sh[threadIdx.x] = v;
    __syncthreads();
    for (int off = 1; off < 1024; off <<= 1) {
        int t = 0;
        if ((int)threadIdx.x >= off) t = sh[threadIdx.x - off];
        __syncthreads();
        sh[threadIdx.x] += t;
        __syncthreads();
    }
    if ((int)threadIdx.x < nb) g_bsumscan[threadIdx.x] = sh[threadIdx.x] - v;
}
__global__ void k_scan3(int n) {
    int gid = blockIdx.x * 1024 + threadIdx.x;
    if (gid < n) {
        int v = g_off[gid] + g_bsumscan[blockIdx.x];
        g_off[gid]    = v;
        g_cursor[gid] = v;
    }
}
__global__ void k_scatter(const void* __restrict__ ei, const float* __restrict__ ea, int e, int n) {
    int i = blockIdx.x * blockDim.x + threadIdx.x;
    if (i >= e) return;
    int r, c;
    load_edge(ei, i, e, r, c);
    if ((unsigned)r >= (unsigned)n || (unsigned)c >= (unsigned)n) return;
    float nm = g_dinv[r] * ea[i] * g_dinv[c];
    int pos = atomicAdd(&g_cursor[c], 1);
    g_edat[pos] = make_int2(r, __float_as_int(nm));
}
// post-scatter, g_cursor[c] == end of segment c

// ================= tf32 mma GEMM, cp.async double-buffered =================
// A pre-rounded tf32 (g_xt / g_hA / g_hB), W pre-rounded (g_Wc + layer*C*C).
// CTA 128x128, 8 warps (32x64 warp tile). Dynamic smem:
//   per stage: X 128x32 fl (16KB, 16B-XOR swizzled) + W 32x136 fl (17KB, pitch 136)
#define WPITCH 136
#define XCH    (128 * 32)
#define WCH    (32 * WPITCH)
#define STAGEF (XCH + WCH)
#define SMEM_DYN (2 * STAGEF * 4)

__global__ void __launch_bounds__(256, 2) k_gemm_mma(int layer, int n) {
    const float* __restrict__ A = (layer == 0) ? g_xt : (layer == 1 ? g_hA : g_hB);
    const float* __restrict__ Wp = g_Wc + (size_t)layer * C * C;

    extern __shared__ float sdy[];
    const uint32_t sbase = smem_u32(sdy);

    const int tid  = threadIdx.x;
    const int wid  = tid >> 5;
    const int lane = tid & 31;
    const int g    = lane >> 2;
    const int tg   = lane & 3;
    const int row0 = blockIdx.x * 128;
    const int mrow = (wid & 3) * 32;
    const int ncol = (wid >> 2) * 64;

    // staging assignments
    const int xrow = tid >> 1;         // 0..127
    const int xh   = tid & 1;          // half-row (16 floats)
    const int wkr  = tid >> 3;         // 0..31 (k row)
    const int wseg = tid & 7;          // 16-float segment

    const bool xok = (row0 + xrow) < n;
    const float* xsrc0 = A + (size_t)(xok ? (row0 + xrow) : 0) * C;
    const int    xzf   = xok ? 16 : 0;
    const uint32_t xsw = (uint32_t)(xrow & 7);   // 16B-chunk XOR swizzle key

    float acc[2][8][4];
#pragma unroll
    for (int i = 0; i < 2; i++)
#pragma unroll
        for (int j = 0; j < 8; j++)
#pragma unroll
            for (int t = 0; t < 4; t++) acc[i][j][t] = 0.0f;

    // ---- stage loader (cp.async, no registers) ----
    auto stage_load = [&](int stage, int kc) {
        uint32_t xb = sbase + stage * (STAGEF * 4);
        uint32_t wb = xb + XCH * 4;
#pragma unroll
        for (int q = 0; q < 4; q++) {
            uint32_t kq = (uint32_t)(xh * 4 + q);
            cp16(xb + xrow * 128 + ((kq ^ xsw) << 4),
                 xsrc0 + kc * 32 + kq * 4, xzf);
        }
#pragma unroll
        for (int q = 0; q < 4; q++) {
            cp16(wb + wkr * (WPITCH * 4) + wseg * 64 + q * 16,
                 Wp + (size_t)(kc * 32 + wkr) * C + wseg * 16 + q * 4, 16);
        }
    };

    stage_load(0, 0); CP_COMMIT();
    stage_load(1, 1); CP_COMMIT();

#pragma unroll
    for (int kc = 0; kc < 4; kc++) {
        if (kc < 3) { CP_WAIT(1); } else { CP_WAIT(0); }
        __syncthreads();

        const uint32_t* xsp = (const uint32_t*)(sdy + (kc & 1) * STAGEF);
        const uint32_t* wsp = xsp + XCH;
#pragma unroll
        for (int s = 0; s < 4; s++) {
            uint32_t af[2][4];
#pragma unroll
            for (int i = 0; i < 2; i++) {
                int arow = mrow + i * 16 + g;
                int q0 = ((2 * s)     ^ g) * 4 + tg;
                int q1 = ((2 * s + 1) ^ g) * 4 + tg;
                af[i][0] = xsp[arow * 32 + q0];
                af[i][1] = xsp[(arow + 8) * 32 + q0];
                af[i][2] = xsp[arow * 32 + q1];
                af[i][3] = xsp[(arow + 8) * 32 + q1];
            }
#pragma unroll
            for (int j = 0; j < 8; j++) {
                uint32_t bf[2];
                int bcol = ncol + j * 8 + g;
                bf[0] = wsp[(s * 8 + tg) * WPITCH + bcol];
                bf[1] = wsp[(s * 8 + tg + 4) * WPITCH + bcol];
                mma_tf32(acc[0][j], af[0], bf);
                mma_tf32(acc[1][j], af[1], bf);
            }
        }
        if (kc < 2) {
            __syncthreads();                 // all reads of this stage done
            stage_load(kc & 1, kc + 2); CP_COMMIT();
        }
    }

    // ---- epilogue: fp32 acc -> fp16 g_xw_h ----
#pragma unroll
    for (int i = 0; i < 2; i++) {
        int r0 = row0 + mrow + i * 16 + g;
        int r1 = r0 + 8;
#pragma unroll
        for (int j = 0; j < 8; j++) {
            int cc = ncol + j * 8 + 2 * tg;
            if (r0 < n) {
                __half2 h = __floats2half2_rn(acc[i][j][0], acc[i][j][1]);
                *(__half2*)(g_xw_h + (size_t)r0 * C + cc) = h;
            }
            if (r1 < n) {
                __half2 h = __floats2half2_rn(acc[i][j][2], acc[i][j][3]);
                *(__half2*)(g_xw_h + (size_t)r1 * C + cc) = h;
            }
        }
    }
}

// ---------------- aggregation (fp16 gathers), outputs tf32-rounded ----------------
__global__ void __launch_bounds__(256) k_agg(const float* __restrict__ bias, int dst, int n) {
    float4* __restrict__ out = dst ? (float4*)g_hB : (float4*)g_hA;
    int warp = (blockIdx.x * blockDim.x + threadIdx.x) >> 5;
    int lane = threadIdx.x & 31;
    if (warp >= n) return;
    float dv = g_dinv[warp];
    float sw = dv * dv;
    uint2 su = *(const uint2*)(g_xw_h + (size_t)warp * C + lane * 4);
    float2 s0 = __half22float2(*(__half2*)&su.x);
    float2 s1 = __half22float2(*(__half2*)&su.y);
    float a0 = sw * s0.x, a1 = sw * s0.y, a2 = sw * s1.x, a3 = sw * s1.y;
    int s = g_off[warp], e = g_cursor[warp];
    for (int j = s; j < e; j++) {
        int2 ed = g_edat[j];
        float nm = __int_as_float(ed.y);
        uint2 u = *(const uint2*)(g_xw_h + (size_t)ed.x * C + lane * 4);
        float2 p0 = __half22float2(*(__half2*)&u.x);
        float2 p1 = __half22float2(*(__half2*)&u.y);
        a0 = fmaf(nm, p0.x, a0);
        a1 = fmaf(nm, p0.y, a1);
        a2 = fmaf(nm, p1.x, a2);
        a3 = fmaf(nm, p1.y, a3);
    }
    float4 bb = ((const float4*)bias)[lane];
    float4 r;
    r.x = rnd_tf32(fmaxf(a0 + bb.x, 0.f));   // pre-round for next layer's tf32 MMA
    r.y = rnd_tf32(fmaxf(a1 + bb.y, 0.f));
    r.z = rnd_tf32(fmaxf(a2 + bb.z, 0.f));
    r.w = rnd_tf32(fmaxf(a3 + bb.w, 0.f));
    out[(size_t)warp * 32 + lane] = r;
}

// ---------------- fused layer-3 aggregation + linear head ----------------
__global__ void __launch_bounds__(256) k_agg_head(const float* __restrict__ bias,
                                                  const float* __restrict__ lw,
                                                  const float* __restrict__ lb,
                                                  float* __restrict__ outp, int n) {
    int warp = (blockIdx.x * blockDim.x + threadIdx.x) >> 5;
    int lane = threadIdx.x & 31;
    if (warp >= n) return;
    float dv = g_dinv[warp];
    float sw = dv * dv;
    uint2 su = *(const uint2*)(g_xw_h + (size_t)warp * C + lane * 4);
    float2 s0 = __half22float2(*(__half2*)&su.x);
    float2 s1 = __half22float2(*(__half2*)&su.y);
    float a0 = sw * s0.x, a1 = sw * s0.y, a2 = sw * s1.x, a3 = sw * s1.y;
    int s = g_off[warp], e = g_cursor[warp];
    for (int j = s; j < e; j++) {
        int2 ed = g_edat[j];
        float nm = __int_as_float(ed.y);
        uint2 u = *(const uint2*)(g_xw_h + (size_t)ed.x * C + lane * 4);
        float2 p0 = __half22float2(*(__half2*)&u.x);
        float2 p1 = __half22float2(*(__half2*)&u.y);
        a0 = fmaf(nm, p0.x, a0);
        a1 = fmaf(nm, p0.y, a1);
        a2 = fmaf(nm, p1.x, a2);
        a3 = fmaf(nm, p1.y, a3);
    }
    float4 bb = ((const float4*)bias)[lane];
    float4 w  = ((const float4*)lw)[lane];
    float sdot = fmaxf(a0 + bb.x, 0.f) * w.x
               + fmaxf(a1 + bb.y, 0.f) * w.y
               + fmaxf(a2 + bb.z, 0.f) * w.z
               + fmaxf(a3 + bb.w, 0.f) * w.w;
#pragma unroll
    for (int o = 16; o; o >>= 1) sdot += __shfl_down_sync(0xffffffffu, sdot, o);
    if (lane == 0) outp[warp] = sdot + lb[0];
}

// ---------------- host launch (kernel launches + one attribute set) ----------------
extern "C" void kernel_launch(void* const* d_in, const int* in_sizes, int n_in,
                              void* d_out, int out_size) {
    const float* x  = (const float*)d_in[0];
    const void*  ei = d_in[1];
    const float* ea = (const float*)d_in[2];
    const float* W1 = (const float*)d_in[3];
    const float* b1 = (const float*)d_in[4];
    const float* W2 = (const float*)d_in[5];
    const float* b2 = (const float*)d_in[6];
    const float* W3 = (const float*)d_in[7];
    const float* b3 = (const float*)d_in[8];
    const float* lw = (const float*)d_in[9];
    const float* lb = (const float*)d_in[10];
    float* outp = (float*)d_out;

    const int n = in_sizes[0] / C;
    const int e = in_sizes[2];

    const int nbE    = (e + 255) / 256;
    const int nbScan = (n + 1023) / 1024;
    const int nbDet  = (2 * e + 255) / 256;
    const int nbG    = (n + 127) / 128;
    const int nbW    = (n * 32 + 255) / 256;
    const int nx4    = n * (C / 4);

    cudaFuncSetAttribute(k_gemm_mma, cudaFuncAttributeMaxDynamicSharedMemorySize, SMEM_DYN);

    // launch #4 is k_gemm_mma -> ncu (-s 5 -c 1) profiles the GEMM
    k_initdetect<<<nbDet, 256>>>((const unsigned int*)ei, 2 * e, n,
                                 (const float4*)x, nx4, W1, W2, W3);       // 1
    k_prep      <<<nbE, 256>>>(ei, ea, e, n);                              // 2
    k_scan1     <<<nbScan, 1024>>>(n);                                     // 3
    k_gemm_mma  <<<nbG, 256, SMEM_DYN>>>(0, n);                            // 4 <- profiled
    k_scan2     <<<1, 1024>>>(nbScan);                                     // 5
    k_scan3     <<<nbScan, 1024>>>(n);                                     // 6
    k_scatter   <<<nbE, 256>>>(ei, ea, e, n);                              // 7
    k_agg       <<<nbW, 256>>>(b1, 0, n);                                  // 8  -> hA
    k_gemm_mma  <<<nbG, 256, SMEM_DYN>>>(1, n);                            // 9
    k_agg       <<<nbW, 256>>>(b2, 1, n);                                  // 10 -> hB
    k_gemm_mma  <<<nbG, 256, SMEM_DYN>>>(2, n);                            // 11
    k_agg_head  <<<nbW, 256>>>(b3, lw, lb, outp, n);                       // 12
}

// round 15
// speedup vs baseline: 1.6520x; 1.0180x over previous
#include <cuda_runtime.h>
#include <cuda_fp16.h>
#include <stdint.h>

#define MAXN 100000
#define MAXE 1600000
#define C    128

// ---------------- static device scratch ----------------
__device__ float  g_deg[MAXN];
__device__ float  g_dinv[MAXN];
__device__ int    g_count[MAXN];
__device__ int    g_off[MAXN];
__device__ int    g_cursor[MAXN];
__device__ int2   g_edat[MAXE];              // (src, norm-bits) grouped by dst
__device__ __half g_xw_h[(size_t)MAXN * C];  // GEMM output, fp16
__device__ float  g_hA[(size_t)MAXN * C];    // tf32(rna)-rounded activations
__device__ float  g_hB[(size_t)MAXN * C];
__device__ float  g_Wc[3 * C * C];           // tf32(rna)-rounded W1|W2|W3
__device__ int    g_idx32 = 0;               // monotonic: 0 = int64 idx, 1 = int32
__device__ int    g_total;                   // CSC allocation ticket

// ---------------- helpers ----------------
__device__ __forceinline__ uint32_t to_tf32(float x) {
    uint32_t r;
    asm("cvt.rna.tf32.f32 %0, %1;" : "=r"(r) : "f"(x));
    return r;
}
__device__ __forceinline__ float rnd_tf32(float x) { return __uint_as_float(to_tf32(x)); }

__device__ __forceinline__ void mma_tf32(float* d, const uint32_t* a, const uint32_t* b) {
    asm volatile(
        "mma.sync.aligned.m16n8k8.row.col.f32.tf32.tf32.f32 "
        "{%0,%1,%2,%3}, {%4,%5,%6,%7}, {%8,%9}, {%0,%1,%2,%3};"
        : "+f"(d[0]), "+f"(d[1]), "+f"(d[2]), "+f"(d[3])
        : "r"(a[0]), "r"(a[1]), "r"(a[2]), "r"(a[3]), "r"(b[0]), "r"(b[1]));
}
__device__ __forceinline__ uint32_t smem_u32(const void* p) {
    uint32_t a;
    asm("{ .reg .u64 t; cvta.to.shared.u64 t, %1; cvt.u32.u64 %0, t; }" : "=r"(a) : "l"(p));
    return a;
}
__device__ __forceinline__ void cp16(uint32_t dst, const void* src, int zf) {
    asm volatile("cp.async.cg.shared.global [%0], [%1], 16, %2;" :: "r"(dst), "l"(src), "r"(zf));
}
#define CP_COMMIT() asm volatile("cp.async.commit_group;" ::: "memory")
#define CP_WAIT(N)  asm volatile("cp.async.wait_group %0;" :: "n"(N) : "memory")

// ---------------- fused init + detect + W pre-round ----------------
__global__ void k_initdetect(const unsigned int* __restrict__ w, int nwords, int n,
                             const float* __restrict__ W1, const float* __restrict__ W2,
                             const float* __restrict__ W3) {
    int i = blockIdx.x * blockDim.x + threadIdx.x;
    if (i < n) { g_deg[i] = 1.0f; g_count[i] = 0; }
    if (i == 0) g_total = 0;
    unsigned int v = (i < nwords && (i & 1)) ? w[i] : 0u;
#pragma unroll
    for (int o = 16; o; o >>= 1) v |= __shfl_down_sync(0xffffffffu, v, o);
    if ((threadIdx.x & 31) == 0 && v) atomicOr(&g_idx32, 1);
    if (i < C * C) {
        g_Wc[i]             = rnd_tf32(W1[i]);
        g_Wc[C * C + i]     = rnd_tf32(W2[i]);
        g_Wc[2 * C * C + i] = rnd_tf32(W3[i]);
    }
}
__device__ __forceinline__ void load_edge(const void* ei, int i, int e, int& r, int& c) {
    if (g_idx32) {
        const int* p = (const int*)ei;
        r = p[i]; c = p[e + i];
    } else {
        const long long* p = (const long long*)ei;
        r = (int)p[i]; c = (int)p[e + i];
    }
}

// ---------------- precompute ----------------
__global__ void k_prep(const void* __restrict__ ei, const float* __restrict__ ea, int e, int n) {
    int i = blockIdx.x * blockDim.x + threadIdx.x;
    if (i >= e) return;
    int r, c;
    load_edge(ei, i, e, r, c);
    if ((unsigned)r >= (unsigned)n || (unsigned)c >= (unsigned)n) return;
    atomicAdd(&g_deg[c], ea[i]);
    atomicAdd(&g_count[c], 1);
}

// dinv + CSC segment allocation (segment order irrelevant; only contiguity matters)
__global__ void k_alloc(int n) {
    int i = blockIdx.x * blockDim.x + threadIdx.x;
    if (i >= n) return;
    g_dinv[i] = rsqrtf(g_deg[i]);
    int pos = atomicAdd(&g_total, g_count[i]);
    g_off[i]    = pos;
    g_cursor[i] = pos;
}

__global__ void k_scatter(const void* __restrict__ ei, const float* __restrict__ ea, int e, int n) {
    int i = blockIdx.x * blockDim.x + threadIdx.x;
    if (i >= e) return;
    int r, c;
    load_edge(ei, i, e, r, c);
    if ((unsigned)r >= (unsigned)n || (unsigned)c >= (unsigned)n) return;
    float nm = g_dinv[r] * ea[i] * g_dinv[c];
    int pos = atomicAdd(&g_cursor[c], 1);
    g_edat[pos] = make_int2(r, __float_as_int(nm));
}
// post-scatter: segment c = [g_off[c], g_cursor[c])

// ================= persistent tf32 mma GEMM, W resident in smem =================
// Grid = one wave (2 CTAs/SM). Each CTA loads W once (128x136 fl = 69.6KB),
// then loops over row-tiles of 128 with a flat double-buffered X chunk pipeline.
#define WPITCH   136
#define XSTG_B   16384
#define SMEM_DYN (2 * XSTG_B + 128 * WPITCH * 4)   // 102400 B

__global__ void __launch_bounds__(256, 2) k_gemm_mma(const float* __restrict__ Xext,
                                                     int layer, int n, int G) {
    const float* __restrict__ A = (layer == 0) ? Xext : (layer == 1 ? g_hA : g_hB);
    const float* __restrict__ Wp = g_Wc + (size_t)layer * C * C;

    extern __shared__ float sdy[];
    const uint32_t sbase = smem_u32(sdy);
    const uint32_t wbase = sbase + 2 * XSTG_B;

    const int tid  = threadIdx.x;
    const int wid  = tid >> 5;
    const int lane = tid & 31;
    const int g    = lane >> 2;
    const int tg   = lane & 3;
    const int bid  = blockIdx.x;
    const int mrow = (wid & 3) * 32;
    const int ncol = (wid >> 2) * 64;

    const int xrow = tid >> 1;
    const int xh   = tid & 1;
    const uint32_t xsw = (uint32_t)(xrow & 7);

    const int tiles = (n + 127) / 128;
    if (bid >= tiles) return;
    const int nt = (tiles - bid + G - 1) / G;
    const int NC = nt * 4;

    // ---- W -> smem once: 128 rows x 512B; 2 threads/row x 16 segs of 16B ----
    {
        int wrow = tid >> 1;
        int s0   = (tid & 1) * 16;
#pragma unroll
        for (int q = 0; q < 16; q++)
            cp16(wbase + wrow * (WPITCH * 4) + (s0 + q) * 16,
                 Wp + (size_t)wrow * C + (s0 + q) * 4, 16);
    }

    auto stage_x = [&](int stage, int c) {
        int T   = bid + (c >> 2) * G;
        int kc  = c & 3;
        int row = T * 128 + xrow;
        bool ok = row < n;
        const float* s = A + (size_t)(ok ? row : 0) * C + kc * 32;
        int zf = ok ? 16 : 0;
        uint32_t xb = sbase + stage * XSTG_B;
#pragma unroll
        for (int q = 0; q < 4; q++) {
            uint32_t kq = (uint32_t)(xh * 4 + q);
            cp16(xb + xrow * 128 + ((kq ^ xsw) << 4), s + kq * 4, zf);
        }
    };

    float acc[2][8][4];
#pragma unroll
    for (int i = 0; i < 2; i++)
#pragma unroll
        for (int j = 0; j < 8; j++)
#pragma unroll
            for (int t = 0; t < 4; t++) acc[i][j][t] = 0.0f;

    stage_x(0, 0); CP_COMMIT();    // group 0 = W + X chunk0
    stage_x(1, 1); CP_COMMIT();    // group 1 = X chunk1

    const uint32_t* wsp = (const uint32_t*)(sdy + 2 * (XSTG_B / 4));

    for (int c = 0; c < NC; c++) {
        if (c < NC - 1) { CP_WAIT(1); } else { CP_WAIT(0); }
        __syncthreads();

        const uint32_t* xsp = (const uint32_t*)(sdy + (c & 1) * (XSTG_B / 4));
        const int kc = c & 3;
#pragma unroll
        for (int s = 0; s < 4; s++) {
            uint32_t af[2][4];
#pragma unroll
            for (int i = 0; i < 2; i++) {
                int arow = mrow + i * 16 + g;
                int q0 = ((2 * s)     ^ g) * 4 + tg;
                int q1 = ((2 * s + 1) ^ g) * 4 + tg;
                af[i][0] = xsp[arow * 32 + q0];
                af[i][1] = xsp[(arow + 8) * 32 + q0];
                af[i][2] = xsp[arow * 32 + q1];
                af[i][3] = xsp[(arow + 8) * 32 + q1];
            }
#pragma unroll
            for (int j = 0; j < 8; j++) {
                uint32_t bf[2];
                int bcol = ncol + j * 8 + g;
                bf[0] = wsp[(kc * 32 + s * 8 + tg) * WPITCH + bcol];
                bf[1] = wsp[(kc * 32 + s * 8 + tg + 4) * WPITCH + bcol];
                mma_tf32(acc[0][j], af[0], bf);
                mma_tf32(acc[1][j], af[1], bf);
            }
        }
        __syncthreads();
        if (c + 2 < NC) { stage_x(c & 1, c + 2); CP_COMMIT(); }

        if (kc == 3) {
            int T  = bid + (c >> 2) * G;
            int rb = T * 128 + mrow;
#pragma unroll
            for (int i = 0; i < 2; i++) {
                int r0 = rb + i * 16 + g;
                int r1 = r0 + 8;
#pragma unroll
                for (int j = 0; j < 8; j++) {
                    int cc = ncol + j * 8 + 2 * tg;
                    if (r0 < n) {
                        __half2 h = __floats2half2_rn(acc[i][j][0], acc[i][j][1]);
                        *(__half2*)(g_xw_h + (size_t)r0 * C + cc) = h;
                    }
                    if (r1 < n) {
                        __half2 h = __floats2half2_rn(acc[i][j][2], acc[i][j][3]);
                        *(__half2*)(g_xw_h + (size_t)r1 * C + cc) = h;
                    }
                }
            }
#pragma unroll
            for (int i = 0; i < 2; i++)
#pragma unroll
                for (int j = 0; j < 8; j++)
#pragma unroll
                    for (int t = 0; t < 4; t++) acc[i][j][t] = 0.0f;
        }
    }
}

// ---------------- aggregation (fp16 gathers), outputs tf32(rna)-rounded ----------------
__global__ void __launch_bounds__(256) k_agg(const float* __restrict__ bias, int dst, int n) {
    float4* __restrict__ out = dst ? (float4*)g_hB : (float4*)g_hA;
    int warp = (blockIdx.x * blockDim.x + threadIdx.x) >> 5;
    int lane = threadIdx.x & 31;
    if (warp >= n) return;
    float dv = g_dinv[warp];
    float sw = dv * dv;
    uint2 su = *(const uint2*)(g_xw_h + (size_t)warp * C + lane * 4);
    float2 s0 = __half22float2(*(__half2*)&su.x);
    float2 s1 = __half22float2(*(__half2*)&su.y);
    float a0 = sw * s0.x, a1 = sw * s0.y, a2 = sw * s1.x, a3 = sw * s1.y;
    int s = g_off[warp], e = g_cursor[warp];
    for (int j = s; j < e; j++) {
        int2 ed = g_edat[j];
        float nm = __int_as_float(ed.y);
        uint2 u = *(const uint2*)(g_xw_h + (size_t)ed.x * C + lane * 4);
        float2 p0 = __half22float2(*(__half2*)&u.x);
        float2 p1 = __half22float2(*(__half2*)&u.y);
        a0 = fmaf(nm, p0.x, a0);
        a1 = fmaf(nm, p0.y, a1);
        a2 = fmaf(nm, p1.x, a2);
        a3 = fmaf(nm, p1.y, a3);
    }
    float4 bb = ((const float4*)bias)[lane];
    float4 r;
    r.x = rnd_tf32(fmaxf(a0 + bb.x, 0.f));
    r.y = rnd_tf32(fmaxf(a1 + bb.y, 0.f));
    r.z = rnd_tf32(fmaxf(a2 + bb.z, 0.f));
    r.w = rnd_tf32(fmaxf(a3 + bb.w, 0.f));
    out[(size_t)warp * 32 + lane] = r;
}

// ---------------- fused layer-3 aggregation + linear head ----------------
__global__ void __launch_bounds__(256) k_agg_head(const float* __restrict__ bias,
                                                  const float* __restrict__ lw,
                                                  const float* __restrict__ lb,
                                                  float* __restrict__ outp, int n) {
    int warp = (blockIdx.x * blockDim.x + threadIdx.x) >> 5;
    int lane = threadIdx.x & 31;
    if (warp >= n) return;
    float dv = g_dinv[warp];
    float sw = dv * dv;
    uint2 su = *(const uint2*)(g_xw_h + (size_t)warp * C + lane * 4);
    float2 s0 = __half22float2(*(__half2*)&su.x);
    float2 s1 = __half22float2(*(__half2*)&su.y);
    float a0 = sw * s0.x, a1 = sw * s0.y, a2 = sw * s1.x, a3 = sw * s1.y;
    int s = g_off[warp], e = g_cursor[warp];
    for (int j = s; j < e; j++) {
        int2 ed = g_edat[j];
        float nm = __int_as_float(ed.y);
        uint2 u = *(const uint2*)(g_xw_h + (size_t)ed.x * C + lane * 4);
        float2 p0 = __half22float2(*(__half2*)&u.x);
        float2 p1 = __half22float2(*(__half2*)&u.y);
        a0 = fmaf(nm, p0.x, a0);
        a1 = fmaf(nm, p0.y, a1);
        a2 = fmaf(nm, p1.x, a2);
        a3 = fmaf(nm, p1.y, a3);
    }
    float4 bb = ((const float4*)bias)[lane];
    float4 w  = ((const float4*)lw)[lane];
    float sdot = fmaxf(a0 + bb.x, 0.f) * w.x
               + fmaxf(a1 + bb.y, 0.f) * w.y
               + fmaxf(a2 + bb.z, 0.f) * w.z
               + fmaxf(a3 + bb.w, 0.f) * w.w;
#pragma unroll
    for (int o = 16; o; o >>= 1) sdot += __shfl_down_sync(0xffffffffu, sdot, o);
    if (lane == 0) outp[warp] = sdot + lb[0];
}

// ---------------- host launch ----------------
extern "C" void kernel_launch(void* const* d_in, const int* in_sizes, int n_in,
                              void* d_out, int out_size) {
    const float* x  = (const float*)d_in[0];
    const void*  ei = d_in[1];
    const float* ea = (const float*)d_in[2];
    const float* W1 = (const float*)d_in[3];
    const float* b1 = (const float*)d_in[4];
    const float* W2 = (const float*)d_in[5];
    const float* b2 = (const float*)d_in[6];
    const float* W3 = (const float*)d_in[7];
    const float* b3 = (const float*)d_in[8];
    const float* lw = (const float*)d_in[9];
    const float* lb = (const float*)d_in[10];
    float* outp = (float*)d_out;

    int n = in_sizes[0] / C;
    int e = in_sizes[2];
    if (n > MAXN) n = MAXN;          // defensive: never overrun static scratch
    if (e > MAXE) e = MAXE;

    const int nbE   = (e + 255) / 256;
    const int nbN   = (n + 255) / 256;
    const int nbDet = (2 * e + 255) / 256;
    const int nbW   = (n * 32 + 255) / 256;
    const int tiles = (n + 127) / 128;
    int G = 2 * 148;
    if (G > tiles) G = tiles;

    cudaFuncSetAttribute(k_gemm_mma, cudaFuncAttributeMaxDynamicSharedMemorySize, SMEM_DYN);

    k_initdetect<<<nbDet, 256>>>((const unsigned int*)ei, 2 * e, n, W1, W2, W3); // 1
    k_prep      <<<nbE, 256>>>(ei, ea, e, n);                               // 2
    k_alloc     <<<nbN, 256>>>(n);                                          // 3
    k_gemm_mma  <<<G, 256, SMEM_DYN>>>(x, 0, n, G);                         // 4 <- profiled
    k_scatter   <<<nbE, 256>>>(ei, ea, e, n);                               // 5
    k_agg       <<<nbW, 256>>>(b1, 0, n);                                   // 6  -> hA
    k_gemm_mma  <<<G, 256, SMEM_DYN>>>(x, 1, n, G);                         // 7
    k_agg       <<<nbW, 256>>>(b2, 1, n);                                   // 8  -> hB
    k_gemm_mma  <<<G, 256, SMEM_DYN>>>(x, 2, n, G);                         // 9
    k_agg_head  <<<nbW, 256>>>(b3, lw, lb, outp, n);                        // 10
}

// round 16
// speedup vs baseline: 1.8644x; 1.1285x over previous
#include <cuda_runtime.h>
#include <cuda_fp16.h>
#include <stdint.h>

#define MAXN 100000
#define MAXE 1600000
#define C    128

// ---------------- static device scratch ----------------
__device__ float  g_deg[MAXN];
__device__ float  g_dinv[MAXN];
__device__ int    g_count[MAXN];
__device__ int    g_off[MAXN];
__device__ int    g_cursor[MAXN];
__device__ int2   g_edat[MAXE];              // (src, norm-bits) grouped by dst
__device__ __half g_xw_h[(size_t)MAXN * C];  // GEMM output, fp16
__device__ __half g_xh[(size_t)MAXN * C];    // fp16 copy of x
__device__ __half g_hA[(size_t)MAXN * C];    // fp16 activations
__device__ __half g_hB[(size_t)MAXN * C];
__device__ __half g_Wh[3 * C * C];           // fp16 W1|W2|W3
__device__ int    g_idx32 = 0;               // monotonic: 0 = int64 idx, 1 = int32
__device__ int    g_total;                   // CSC allocation ticket

// ---------------- helpers ----------------
__device__ __forceinline__ uint32_t smem_u32(const void* p) {
    uint32_t a;
    asm("{ .reg .u64 t; cvta.to.shared.u64 t, %1; cvt.u32.u64 %0, t; }" : "=r"(a) : "l"(p));
    return a;
}
__device__ __forceinline__ void cp16(uint32_t dst, const void* src, int zf) {
    asm volatile("cp.async.cg.shared.global [%0], [%1], 16, %2;" :: "r"(dst), "l"(src), "r"(zf));
}
#define CP_COMMIT() asm volatile("cp.async.commit_group;" ::: "memory")
#define CP_WAIT(N)  asm volatile("cp.async.wait_group %0;" :: "n"(N) : "memory")

__device__ __forceinline__ void ldsm4(uint32_t* r, uint32_t addr) {
    asm volatile("ldmatrix.sync.aligned.m8n8.x4.shared.b16 {%0,%1,%2,%3}, [%4];"
                 : "=r"(r[0]), "=r"(r[1]), "=r"(r[2]), "=r"(r[3]) : "r"(addr));
}
__device__ __forceinline__ void ldsm4t(uint32_t* r, uint32_t addr) {
    asm volatile("ldmatrix.sync.aligned.m8n8.x4.trans.shared.b16 {%0,%1,%2,%3}, [%4];"
                 : "=r"(r[0]), "=r"(r[1]), "=r"(r[2]), "=r"(r[3]) : "r"(addr));
}
__device__ __forceinline__ void mma_f16(float* d, const uint32_t* a, uint32_t b0, uint32_t b1) {
    asm volatile(
        "mma.sync.aligned.m16n8k16.row.col.f32.f16.f16.f32 "
        "{%0,%1,%2,%3}, {%4,%5,%6,%7}, {%8,%9}, {%0,%1,%2,%3};"
        : "+f"(d[0]), "+f"(d[1]), "+f"(d[2]), "+f"(d[3])
        : "r"(a[0]), "r"(a[1]), "r"(a[2]), "r"(a[3]), "r"(b0), "r"(b1));
}

// ---------------- fused init + detect + fp16 pre-convert ----------------
__global__ void k_initdetect(const unsigned int* __restrict__ w, int nwords, int n,
                             const float4* __restrict__ x4,
                             const float* __restrict__ W1, const float* __restrict__ W2,
                             const float* __restrict__ W3) {
    int i = blockIdx.x * blockDim.x + threadIdx.x;
    if (i < n) { g_deg[i] = 1.0f; g_count[i] = 0; }
    if (i == 0) g_total = 0;
    unsigned int v = (i < nwords && (i & 1)) ? w[i] : 0u;
#pragma unroll
    for (int o = 16; o; o >>= 1) v |= __shfl_down_sync(0xffffffffu, v, o);
    if ((threadIdx.x & 31) == 0 && v) atomicOr(&g_idx32, 1);
    if (i < n * (C / 4)) {                       // x -> fp16 (4 floats / thread)
        float4 t = x4[i];
        __half2 h0 = __floats2half2_rn(t.x, t.y);
        __half2 h1 = __floats2half2_rn(t.z, t.w);
        *(uint2*)(g_xh + (size_t)i * 4) = make_uint2(*(uint32_t*)&h0, *(uint32_t*)&h1);
    }
    if (i < C * C) {
        g_Wh[i]             = __float2half_rn(W1[i]);
        g_Wh[C * C + i]     = __float2half_rn(W2[i]);
        g_Wh[2 * C * C + i] = __float2half_rn(W3[i]);
    }
}
__device__ __forceinline__ void load_edge(const void* ei, int i, int e, int& r, int& c) {
    if (g_idx32) {
        const int* p = (const int*)ei;
        r = p[i]; c = p[e + i];
    } else {
        const long long* p = (const long long*)ei;
        r = (int)p[i]; c = (int)p[e + i];
    }
}

// ---------------- precompute ----------------
__global__ void k_prep(const void* __restrict__ ei, const float* __restrict__ ea, int e, int n) {
    int i = blockIdx.x * blockDim.x + threadIdx.x;
    if (i >= e) return;
    int r, c;
    load_edge(ei, i, e, r, c);
    if ((unsigned)r >= (unsigned)n || (unsigned)c >= (unsigned)n) return;
    atomicAdd(&g_deg[c], ea[i]);
    atomicAdd(&g_count[c], 1);
}

__global__ void k_alloc(int n) {
    int i = blockIdx.x * blockDim.x + threadIdx.x;
    if (i >= n) return;
    g_dinv[i] = rsqrtf(g_deg[i]);
    int pos = atomicAdd(&g_total, g_count[i]);
    g_off[i]    = pos;
    g_cursor[i] = pos;
}

__global__ void k_scatter(const void* __restrict__ ei, const float* __restrict__ ea, int e, int n) {
    int i = blockIdx.x * blockDim.x + threadIdx.x;
    if (i >= e) return;
    int r, c;
    load_edge(ei, i, e, r, c);
    if ((unsigned)r >= (unsigned)n || (unsigned)c >= (unsigned)n) return;
    float nm = g_dinv[r] * ea[i] * g_dinv[c];
    int pos = atomicAdd(&g_cursor[c], 1);
    g_edat[pos] = make_int2(r, __float_as_int(nm));
}
// post-scatter: segment c = [g_off[c], g_cursor[c])

// ================= persistent fp16 mma GEMM (ldmatrix), W resident =================
// 128x128 tile, 8 warps (32x64 warp tiles). fp16 smem rows pitched 272B
// (conflict-free ldmatrix: bank step 4/row). W 34KB resident; X 2x34KB stages.
#define PITCHB   272                          // bytes per 128-half row
#define XSTG_B   (128 * PITCHB)               // 34816
#define SMEM_DYN (3 * XSTG_B)                 // 104448

__global__ void __launch_bounds__(256, 2) k_gemm_mma(int layer, int n, int G) {
    const __half* __restrict__ A = (layer == 0) ? g_xh : (layer == 1 ? g_hA : g_hB);
    const __half* __restrict__ Wp = g_Wh + (size_t)layer * C * C;

    extern __shared__ char sdy[];
    const uint32_t sbase = smem_u32(sdy);
    const uint32_t wbase = sbase + 2 * XSTG_B;

    const int tid  = threadIdx.x;
    const int wid  = tid >> 5;
    const int lane = tid & 31;
    const int g    = lane >> 2;
    const int tg   = lane & 3;
    const int bid  = blockIdx.x;
    const int mrow = (wid & 3) * 32;
    const int ncol = (wid >> 2) * 64;

    const int tiles = (n + 127) / 128;
    if (bid >= tiles) return;
    const int nt = (tiles - bid + G - 1) / G;

    // ldmatrix lane offset: rows (l&7)+((l>>3)&1)*8, 16B half-chunk sel (l>>4)&1
    const uint32_t lrow = (uint32_t)((lane & 7) + ((lane >> 3) & 1) * 8);
    const uint32_t lhi  = (uint32_t)((lane >> 4) & 1);
    const uint32_t aoff = lrow * PITCHB + lhi * 16;                 // + kstep*32
    const uint32_t boff = lrow * PITCHB + lhi * 16 + (uint32_t)ncol * 2;  // + jj*32 + kstep*16*PITCHB

    // staging: thread t -> row t>>1, 8 chunks of 16B
    const int srow = tid >> 1;
    const int sc0  = (tid & 1) * 8;

    // ---- W -> smem once ----
#pragma unroll
    for (int q = 0; q < 8; q++)
        cp16(wbase + srow * PITCHB + (sc0 + q) * 16,
             Wp + (size_t)srow * C + (sc0 + q) * 8, 16);

    auto stage_x = [&](int stage, int t) {
        int T   = bid + t * G;
        int row = T * 128 + srow;
        bool ok = row < n;
        const __half* s = A + (size_t)(ok ? row : 0) * C;
        int zf = ok ? 16 : 0;
        uint32_t xb = sbase + stage * XSTG_B + srow * PITCHB;
#pragma unroll
        for (int q = 0; q < 8; q++)
            cp16(xb + (sc0 + q) * 16, s + (sc0 + q) * 8, zf);
    };

    stage_x(0, 0); CP_COMMIT();    // group 0 = W + X tile0
    if (nt > 1) { stage_x(1, 1); }
    CP_COMMIT();                   // group 1 = X tile1 (possibly empty)

    for (int t = 0; t < nt; t++) {
        if (t < nt - 1) { CP_WAIT(1); } else { CP_WAIT(0); }
        __syncthreads();

        const uint32_t xs = sbase + (uint32_t)(t & 1) * XSTG_B;

        float acc[2][8][4];
#pragma unroll
        for (int i = 0; i < 2; i++)
#pragma unroll
            for (int j = 0; j < 8; j++)
#pragma unroll
                for (int q = 0; q < 4; q++) acc[i][j][q] = 0.0f;

#pragma unroll
        for (int ks = 0; ks < 8; ks++) {
            uint32_t af[2][4], bf[4][4];
            ldsm4(af[0], xs + (uint32_t)(mrow)      * PITCHB + aoff + ks * 32);
            ldsm4(af[1], xs + (uint32_t)(mrow + 16) * PITCHB + aoff + ks * 32);
#pragma unroll
            for (int jj = 0; jj < 4; jj++)
                ldsm4t(bf[jj], wbase + (uint32_t)(ks * 16) * PITCHB + boff + jj * 32);
#pragma unroll
            for (int j = 0; j < 8; j++) {
                uint32_t b0 = bf[j >> 1][(j & 1) * 2];
                uint32_t b1 = bf[j >> 1][(j & 1) * 2 + 1];
                mma_f16(acc[0][j], af[0], b0, b1);
                mma_f16(acc[1][j], af[1], b0, b1);
            }
        }
        __syncthreads();                       // stage reads done before overwrite
        if (t + 2 < nt) { stage_x(t & 1, t + 2); }
        CP_COMMIT();                           // keep group count in lockstep

        // ---- epilogue: fp32 acc -> fp16 g_xw_h ----
        int rb = (bid + t * G) * 128 + mrow;
#pragma unroll
        for (int i = 0; i < 2; i++) {
            int r0 = rb + i * 16 + g;
            int r1 = r0 + 8;
#pragma unroll
            for (int j = 0; j < 8; j++) {
                int cc = ncol + j * 8 + 2 * tg;
                if (r0 < n) {
                    __half2 h = __floats2half2_rn(acc[i][j][0], acc[i][j][1]);
                    *(__half2*)(g_xw_h + (size_t)r0 * C + cc) = h;
                }
                if (r1 < n) {
                    __half2 h = __floats2half2_rn(acc[i][j][2], acc[i][j][3]);
                    *(__half2*)(g_xw_h + (size_t)r1 * C + cc) = h;
                }
            }
        }
    }
}

// ---------------- aggregation (fp16 gathers), fp16 activation output ----------------
__global__ void __launch_bounds__(256) k_agg(const float* __restrict__ bias, int dst, int n) {
    __half* __restrict__ out = dst ? g_hB : g_hA;
    int warp = (blockIdx.x * blockDim.x + threadIdx.x) >> 5;
    int lane = threadIdx.x & 31;
    if (warp >= n) return;
    float dv = g_dinv[warp];
    float sw = dv * dv;
    uint2 su = *(const uint2*)(g_xw_h + (size_t)warp * C + lane * 4);
    float2 s0 = __half22float2(*(__half2*)&su.x);
    float2 s1 = __half22float2(*(__half2*)&su.y);
    float a0 = sw * s0.x, a1 = sw * s0.y, a2 = sw * s1.x, a3 = sw * s1.y;
    int s = g_off[warp], e = g_cursor[warp];
    for (int j = s; j < e; j++) {
        int2 ed = g_edat[j];
        float nm = __int_as_float(ed.y);
        uint2 u = *(const uint2*)(g_xw_h + (size_t)ed.x * C + lane * 4);
        float2 p0 = __half22float2(*(__half2*)&u.x);
        float2 p1 = __half22float2(*(__half2*)&u.y);
        a0 = fmaf(nm, p0.x, a0);
        a1 = fmaf(nm, p0.y, a1);
        a2 = fmaf(nm, p1.x, a2);
        a3 = fmaf(nm, p1.y, a3);
    }
    float4 bb = ((const float4*)bias)[lane];
    __half2 h0 = __floats2half2_rn(fmaxf(a0 + bb.x, 0.f), fmaxf(a1 + bb.y, 0.f));
    __half2 h1 = __floats2half2_rn(fmaxf(a2 + bb.z, 0.f), fmaxf(a3 + bb.w, 0.f));
    *(uint2*)(out + (size_t)warp * C + lane * 4) = make_uint2(*(uint32_t*)&h0, *(uint32_t*)&h1);
}

// ---------------- fused layer-3 aggregation + linear head ----------------
__global__ void __launch_bounds__(256) k_agg_head(const float* __restrict__ bias,
                                                  const float* __restrict__ lw,
                                                  const float* __restrict__ lb,
                                                  float* __restrict__ outp, int n) {
    int warp = (blockIdx.x * blockDim.x + threadIdx.x) >> 5;
    int lane = threadIdx.x & 31;
    if (warp >= n) return;
    float dv = g_dinv[warp];
    float sw = dv * dv;
    uint2 su = *(const uint2*)(g_xw_h + (size_t)warp * C + lane * 4);
    float2 s0 = __half22float2(*(__half2*)&su.x);
    float2 s1 = __half22float2(*(__half2*)&su.y);
    float a0 = sw * s0.x, a1 = sw * s0.y, a2 = sw * s1.x, a3 = sw * s1.y;
    int s = g_off[warp], e = g_cursor[warp];
    for (int j = s; j < e; j++) {
        int2 ed = g_edat[j];
        float nm = __int_as_float(ed.y);
        uint2 u = *(const uint2*)(g_xw_h + (size_t)ed.x * C + lane * 4);
        float2 p0 = __half22float2(*(__half2*)&u.x);
        float2 p1 = __half22float2(*(__half2*)&u.y);
        a0 = fmaf(nm, p0.x, a0);
        a1 = fmaf(nm, p0.y, a1);
        a2 = fmaf(nm, p1.x, a2);
        a3 = fmaf(nm, p1.y, a3);
    }
    float4 bb = ((const float4*)bias)[lane];
    float4 w  = ((const float4*)lw)[lane];
    float sdot = fmaxf(a0 + bb.x, 0.f) * w.x
               + fmaxf(a1 + bb.y, 0.f) * w.y
               + fmaxf(a2 + bb.z, 0.f) * w.z
               + fmaxf(a3 + bb.w, 0.f) * w.w;
#pragma unroll
    for (int o = 16; o; o >>= 1) sdot += __shfl_down_sync(0xffffffffu, sdot, o);
    if (lane == 0) outp[warp] = sdot + lb[0];
}

// ---------------- host launch ----------------
extern "C" void kernel_launch(void* const* d_in, const int* in_sizes, int n_in,
                              void* d_out, int out_size) {
    const float* x  = (const float*)d_in[0];
    const void*  ei = d_in[1];
    const float* ea = (const float*)d_in[2];
    const float* W1 = (const float*)d_in[3];
    const float* b1 = (const float*)d_in[4];
    const float* W2 = (const float*)d_in[5];
    const float* b2 = (const float*)d_in[6];
    const float* W3 = (const float*)d_in[7];
    const float* b3 = (const float*)d_in[8];
    const float* lw = (const float*)d_in[9];
    const float* lb = (const float*)d_in[10];
    float* outp = (float*)d_out;

    int n = in_sizes[0] / C;
    int e = in_sizes[2];
    if (n > MAXN) n = MAXN;
    if (e > MAXE) e = MAXE;

    const int nbE   = (e + 255) / 256;
    const int nbN   = (n + 255) / 256;
    const int nbDet = (2 * e + 255) / 256;     // also covers n*32 fp16-convert threads
    const int nbW   = (n * 32 + 255) / 256;
    const int tiles = (n + 127) / 128;
    int G = 2 * 148;
    if (G > tiles) G = tiles;

    cudaFuncSetAttribute(k_gemm_mma, cudaFuncAttributeMaxDynamicSharedMemorySize, SMEM_DYN);

    k_initdetect<<<nbDet, 256>>>((const unsigned int*)ei, 2 * e, n,
                                 (const float4*)x, W1, W2, W3);             // 1
    k_prep      <<<nbE, 256>>>(ei, ea, e, n);                               // 2
    k_alloc     <<<nbN, 256>>>(n);                                          // 3
    k_gemm_mma  <<<G, 256, SMEM_DYN>>>(0, n, G);                            // 4 <- profiled
    k_scatter   <<<nbE, 256>>>(ei, ea, e, n);                               // 5
    k_agg       <<<nbW, 256>>>(b1, 0, n);                                   // 6  -> hA
    k_gemm_mma  <<<G, 256, SMEM_DYN>>>(1, n, G);                            // 7
    k_agg       <<<nbW, 256>>>(b2, 1, n);                                   // 8  -> hB
    k_gemm_mma  <<<G, 256, SMEM_DYN>>>(2, n, G);                            // 9
    k_agg_head  <<<nbW, 256>>>(b3, lw, lb, outp, n);                        // 10
}